// round 11
// baseline (speedup 1.0000x reference)
#include <cuda_runtime.h>
#include <cuda_bf16.h>
#include <cstdint>
#include <math.h>

#define B_      4
#define T_      4096
#define HID_    768
#define H_      12
#define D_      64
#define BH_     48
#define NBUCK_  32
#define NBTOT_  64
#define TOTAL_  8192
#define NCH_    64
#define CL_     128
#define M_      (B_*T_)      // 16384
#define PADK    65

// ---------------- scratch (static device globals; no allocation) ----------------
__device__ float g_qk[BH_*T_*D_];            // [bh][t][d]
__device__ float g_v [BH_*T_*D_];
__device__ int   g_bucket[BH_*TOTAL_];
__device__ int   g_sidx[BH_*TOTAL_];
__device__ int   g_undo[BH_*TOTAL_];
__device__ int   g_bbase[BH_*NBTOT_];
__device__ float g_so  [BH_*TOTAL_*D_];
__device__ float g_slog[BH_*TOTAL_];
__device__ float g_attn[M_*HID_];
__device__ float g_tmp [M_*HID_];
// bf16 split planes: A-side (16384x768 per split), B-side (768x768 per split)
__device__ __nv_bfloat16 g_as[3 * M_ * HID_];
__device__ __nv_bfloat16 g_bs[3 * HID_ * HID_];

__device__ __forceinline__ unsigned int smem_u32(const void* p) {
    unsigned int a;
    asm("{ .reg .u64 t; cvta.to.shared.u64 t, %1; cvt.u32.u64 %0, t; }" : "=r"(a) : "l"(p));
    return a;
}
__device__ __forceinline__ void ldm_x4(unsigned int& r0, unsigned int& r1,
                                       unsigned int& r2, unsigned int& r3,
                                       unsigned int addr) {
    asm volatile("ldmatrix.sync.aligned.m8n8.x4.shared.b16 {%0,%1,%2,%3}, [%4];"
                 : "=r"(r0), "=r"(r1), "=r"(r2), "=r"(r3) : "r"(addr));
}
__device__ __forceinline__ void mma_bf16(float& c0, float& c1, float& c2, float& c3,
                                         unsigned int a0, unsigned int a1,
                                         unsigned int a2, unsigned int a3,
                                         unsigned int b0, unsigned int b1) {
    asm volatile("mma.sync.aligned.m16n8k16.row.col.f32.bf16.bf16.f32 "
                 "{%0,%1,%2,%3}, {%4,%5,%6,%7}, {%8,%9}, {%0,%1,%2,%3};"
                 : "+f"(c0), "+f"(c1), "+f"(c2), "+f"(c3)
                 : "r"(a0), "r"(a1), "r"(a2), "r"(a3), "r"(b0), "r"(b1));
}
__device__ __forceinline__ void cp8(unsigned int dst, const void* src) {
    asm volatile("cp.async.ca.shared.global [%0], [%1], 8;" :: "r"(dst), "l"(src));
}
__device__ __forceinline__ void cp_commit() {
    asm volatile("cp.async.commit_group;" ::: "memory");
}

// ---------------- fp32 -> ns bf16 split planes ----------------
// which: 0 -> g_as, 1 -> g_bs     insel: 0 -> src param, 1 -> g_attn, 2 -> g_tmp
__global__ __launch_bounds__(256) void split_kernel(const float* __restrict__ srcp,
                                                    int n4, int ns, int which, int insel)
{
    int idx = blockIdx.x * 256 + threadIdx.x;
    if (idx >= n4) return;
    const float* src = (insel == 0) ? srcp : (insel == 1 ? (const float*)g_attn : (const float*)g_tmp);
    float4 v = ((const float4*)src)[idx];
    __nv_bfloat16* dst = which ? g_bs : g_as;
    size_t stride = which ? (size_t)HID_ * HID_ : (size_t)M_ * HID_;
    float rx = v.x, ry = v.y, rz = v.z, rw = v.w;
    for (int s = 0; s < ns; s++) {
        __nv_bfloat16 bx = __float2bfloat16(rx), by = __float2bfloat16(ry);
        __nv_bfloat16 bz = __float2bfloat16(rz), bw = __float2bfloat16(rw);
        rx -= __bfloat162float(bx); ry -= __bfloat162float(by);
        rz -= __bfloat162float(bz); rw -= __bfloat162float(bw);
        uint2 u;
        u.x = (unsigned int)__bfloat16_as_ushort(bx) | ((unsigned int)__bfloat16_as_ushort(by) << 16);
        u.y = (unsigned int)__bfloat16_as_ushort(bz) | ((unsigned int)__bfloat16_as_ushort(bw) << 16);
        *(uint2*)(dst + s * stride + (size_t)idx * 4) = u;
    }
}

// ================= split-bf16 GEMM via mma.sync + cp.async pipeline =================
// C[M,768] = A[M,768] @ W[768,768]^T (+bias), A/B pre-split in g_as/g_bs
// block tile M=128, N=128, K-chunk=32; warp tile 32x64; 8 warps (4x2); 2-stage cp.async
// smem plane layout: plane p (A: p=0..ns-1, B: p=ns..2ns-1) at p*5120 halves
// outmode: 0=Cout(+bias), 3=g_tmp(+bias), 1=g_qk merged-head, 2=g_v merged-head
#define LDA_ 40                      // halves per row (80B stride, ldmatrix conflict-free)
#define SP_H (128*LDA_)              // 5120 halves per plane (A and B both 128 rows)
#define GEMM_SMEM_MAX (2 * 3 * 2 * SP_H * 2)   // 2 stages x (3 A + 3 B planes) x 2B = 122880

__global__ __launch_bounds__(256) void mma_gemm_kernel(
    const float* __restrict__ bias, float* __restrict__ Cout,
    int outmode, int ns)
{
    extern __shared__ char smem[];
    unsigned int sbase = smem_u32(smem);

    int tid = threadIdx.x, wid = tid >> 5, lane = tid & 31;
    int bm = blockIdx.y * 128, bn = blockIdx.x * 128;
    int wm = (wid & 3) * 32;
    int wn = (wid >> 2) * 64;

    const int np = (ns == 2) ? 3 : 6;
    const int PA[6] = {0, 0, 1, 1, 0, 2};
    const int PB[6] = {0, 1, 0, 1, 2, 0};
    const unsigned int stage_b = (unsigned int)(2 * ns * SP_H * 2);   // bytes per stage

    float acc[2][8][4];
#pragma unroll
    for (int mi = 0; mi < 2; mi++)
#pragma unroll
        for (int ni = 0; ni < 8; ni++)
#pragma unroll
            for (int q = 0; q < 4; q++) acc[mi][ni][q] = 0.f;

    int arow = tid >> 3, aqc = tid & 7;      // 32 rows covered, x4 iters -> 128 rows
    int ra  = (lane & 7) + ((lane >> 3) & 1) * 8;
    int aco = (lane >> 4) * 8;
    unsigned int aoff[2];
#pragma unroll
    for (int mi = 0; mi < 2; mi++)
        aoff[mi] = (unsigned int)((wm + mi*16 + ra) * LDA_ + aco);
    int rb  = lane & 7;
    int bco = ((lane >> 3) & 1) * 8;
    unsigned int boff[4];
#pragma unroll
    for (int g = 0; g < 4; g++)
        boff[g] = (unsigned int)((wn + (g*2 + (lane >> 4))*8 + rb) * LDA_ + bco);

    const size_t ASZ = (size_t)M_ * HID_;
    const size_t BSZ = (size_t)HID_ * HID_;

    auto issue = [&](int kc, int buf) {
        int k0 = kc * 32;
        unsigned int sbuf = sbase + buf * stage_b;
        for (int s = 0; s < ns; s++) {
            const __nv_bfloat16* ga = g_as + s * ASZ + (size_t)(bm + arow) * HID_ + k0 + aqc * 4;
            unsigned int da = sbuf + (unsigned int)((s * SP_H + arow * LDA_ + aqc * 4) * 2);
#pragma unroll
            for (int i = 0; i < 4; i++)
                cp8(da + (unsigned int)(i * 32 * LDA_ * 2), ga + (size_t)i * 32 * HID_);
            const __nv_bfloat16* gb = g_bs + s * BSZ + (size_t)(bn + arow) * HID_ + k0 + aqc * 4;
            unsigned int db = sbuf + (unsigned int)(((ns + s) * SP_H + arow * LDA_ + aqc * 4) * 2);
#pragma unroll
            for (int i = 0; i < 4; i++)
                cp8(db + (unsigned int)(i * 32 * LDA_ * 2), gb + (size_t)i * 32 * HID_);
        }
        cp_commit();
    };

    issue(0, 0);

    for (int kc = 0; kc < 24; kc++) {
        if (kc < 23) {
            issue(kc + 1, (kc + 1) & 1);
            asm volatile("cp.async.wait_group 1;" ::: "memory");
        } else {
            asm volatile("cp.async.wait_group 0;" ::: "memory");
        }
        __syncthreads();

        unsigned int sbuf = sbase + (kc & 1) * stage_b;
        for (int p = 0; p < np; p++) {
            unsigned int pa = sbuf + (unsigned int)(PA[p] * SP_H * 2);
            unsigned int pb = sbuf + (unsigned int)((ns + PB[p]) * SP_H * 2);
#pragma unroll
            for (int k16 = 0; k16 < 2; k16++) {
                unsigned int kb = (unsigned int)(k16 * 16 * 2);
                unsigned int a[2][4], b[4][4];
#pragma unroll
                for (int mi = 0; mi < 2; mi++)
                    ldm_x4(a[mi][0], a[mi][1], a[mi][2], a[mi][3], pa + aoff[mi]*2 + kb);
#pragma unroll
                for (int g = 0; g < 4; g++)
                    ldm_x4(b[g][0], b[g][1], b[g][2], b[g][3], pb + boff[g]*2 + kb);
#pragma unroll
                for (int mi = 0; mi < 2; mi++) {
#pragma unroll
                    for (int ni = 0; ni < 8; ni++) {
                        unsigned int b0 = b[ni >> 1][(ni & 1) * 2];
                        unsigned int b1 = b[ni >> 1][(ni & 1) * 2 + 1];
                        mma_bf16(acc[mi][ni][0], acc[mi][ni][1], acc[mi][ni][2], acc[mi][ni][3],
                                 a[mi][0], a[mi][1], a[mi][2], a[mi][3], b0, b1);
                    }
                }
            }
        }
        __syncthreads();
    }

    // ---- epilogue ----
#pragma unroll
    for (int mi = 0; mi < 2; mi++) {
#pragma unroll
        for (int ni = 0; ni < 8; ni++) {
            int r0  = bm + wm + mi*16 + (lane >> 2);
            int col = bn + wn + ni*8 + (lane & 3)*2;
            float b0 = 0.f, b1 = 0.f;
            if (outmode == 0 || outmode == 3) { b0 = bias[col]; b1 = bias[col+1]; }
            float2 o0 = make_float2(acc[mi][ni][0] + b0, acc[mi][ni][1] + b1);
            float2 o1 = make_float2(acc[mi][ni][2] + b0, acc[mi][ni][3] + b1);
            if (outmode == 0 || outmode == 3) {
                float* dst = (outmode == 0) ? Cout : g_tmp;
                *(float2*)(dst + (size_t)r0     * HID_ + col) = o0;
                *(float2*)(dst + (size_t)(r0+8) * HID_ + col) = o1;
            } else {
                float* dst = (outmode == 1) ? g_qk : g_v;
                int h = col >> 6, dd = col & 63;
                int b_0 = r0 >> 12, t_0 = r0 & (T_-1);
                int b_1 = (r0+8) >> 12, t_1 = (r0+8) & (T_-1);
                *(float2*)(dst + ((size_t)(b_0 * H_ + h) * T_ + t_0) * D_ + dd) = o0;
                *(float2*)(dst + ((size_t)(b_1 * H_ + h) * T_ + t_1) * D_ + dd) = o1;
            }
        }
    }
}

// ---------------- LSH bucketing: warp per (bh, t) ----------------
__global__ __launch_bounds__(256) void bucket_kernel(const float* __restrict__ rot)
{
    __shared__ float srot[D_ * 32];
    int tid = threadIdx.x;
    for (int i = tid; i < D_ * 32; i += 256) srot[i] = rot[i];
    __syncthreads();

    int lane = tid & 31;
    int wid  = tid >> 5;
    int row  = blockIdx.x * 8 + wid;
    int bh   = row >> 12;
    int t    = row & (T_-1);

    const float* q = g_qk + ((size_t)bh * T_ + t) * D_;
    float q0 = q[lane], q1 = q[lane + 32];
    float r = 0.f;
#pragma unroll
    for (int d = 0; d < 32; d++)
        r = fmaf(__shfl_sync(0xffffffffu, q0, d), srot[d * 32 + lane], r);
#pragma unroll
    for (int d = 0; d < 32; d++)
        r = fmaf(__shfl_sync(0xffffffffu, q1, d), srot[(d + 32) * 32 + lane], r);

    int i = lane & 15;
    float nr = -r;
    float v; int idx;
    if (r >= nr) { v = r;  idx = i; } else { v = nr; idx = i + 16; }
#pragma unroll
    for (int off = 8; off > 0; off >>= 1) {
        float ov = __shfl_down_sync(0xffffffffu, v,   off, 16);
        int   oi = __shfl_down_sync(0xffffffffu, idx, off, 16);
        if (ov > v || (ov == v && oi < idx)) { v = ov; idx = oi; }
    }
    if (i == 0) {
        int hash = lane >> 4;
        g_bucket[bh * TOTAL_ + hash * T_ + t] = idx + hash * NBUCK_;
    }
}

// ---------------- histogram + exclusive scan per bh ----------------
__global__ __launch_bounds__(256) void hist_kernel()
{
    __shared__ int h[NBTOT_];
    int bh = blockIdx.x;
    int tid = threadIdx.x;
    if (tid < NBTOT_) h[tid] = 0;
    __syncthreads();
    const int* bp = g_bucket + bh * TOTAL_;
    for (int j = tid; j < TOTAL_; j += 256) atomicAdd(&h[bp[j]], 1);
    __syncthreads();
    if (tid == 0) {
        int run = 0;
        for (int b = 0; b < NBTOT_; b++) { g_bbase[bh * NBTOT_ + b] = run; run += h[b]; }
    }
}

// ---------------- stable scatter: one block per (bucket, bh) ----------------
__global__ __launch_bounds__(256) void scatter_kernel()
{
    int bh  = blockIdx.y;
    int myb = blockIdx.x;
    int tid = threadIdx.x;
    const int* bp = g_bucket + bh * TOTAL_;
    int j0 = tid * 32;
    int cnt = 0;
    for (int k = 0; k < 32; k++) cnt += (bp[j0 + k] == myb);

    __shared__ int s[256];
    s[tid] = cnt;
    __syncthreads();
    for (int off = 1; off < 256; off <<= 1) {
        int v = (tid >= off) ? s[tid - off] : 0;
        __syncthreads();
        s[tid] += v;
        __syncthreads();
    }
    int pos = g_bbase[bh * NBTOT_ + myb] + s[tid] - cnt;
    for (int k = 0; k < 32; k++) {
        int j = j0 + k;
        if (bp[j] == myb) {
            g_sidx[bh * TOTAL_ + pos] = j;
            g_undo[bh * TOTAL_ + j]   = pos;
            pos++;
        }
    }
}

// ---------------- chunked LSH attention: one block per (chunk, bh) ----------------
#define ATTN_SMEM_FLOATS (128*PADK + 256*PADK + 256*PADK + 8*16*PADK)
#define ATTN_SMEM_BYTES  (ATTN_SMEM_FLOATS*4 + (128+256+128+256)*4)

__global__ __launch_bounds__(256, 1) void attn_kernel(const float* __restrict__ mask)
{
    extern __shared__ float smem_f[];
    float* sq = smem_f;
    float* sk = sq + 128*PADK;
    float* sv = sk + 256*PADK;
    float* sp = sv + 256*PADK;
    int*   tq = (int*)(sp + 8*16*PADK);
    int*   tk = tq + 128;
    int*   mq = tk + 256;
    int*   mk = mq + 128;

    int c   = blockIdx.x;
    int bh  = blockIdx.y;
    int tid = threadIdx.x;
    int base = bh * TOTAL_;
    const float* mrow = mask + (bh / H_) * T_;

    if (tid < 128) {
        int si = g_sidx[base + c * CL_ + tid];
        int tp = si & (T_-1);
        tq[tid] = tp;
        mq[tid] = (mrow[tp] != 0.f);
    }
    {
        int j  = tid;
        int cp = (c + NCH_ - 1) & (NCH_ - 1);
        int spos = (j < CL_) ? (c * CL_ + j) : (cp * CL_ + (j - CL_));
        int si = g_sidx[base + spos];
        int tp = si & (T_-1);
        tk[j] = tp;
        mk[j] = (mrow[tp] != 0.f);
    }
    __syncthreads();

    const float* qkb = g_qk + (size_t)bh * T_ * D_;
    const float* vb  = g_v  + (size_t)bh * T_ * D_;
    for (int idx = tid; idx < 128 * 64; idx += 256) {
        int r = idx >> 6, d = idx & 63;
        sq[r * PADK + d] = qkb[(size_t)tq[r] * D_ + d];
    }
    for (int idx = tid; idx < 256 * 64; idx += 256) {
        int r = idx >> 6, d = idx & 63;
        sk[r * PADK + d] = qkb[(size_t)tk[r] * D_ + d];
        sv[r * PADK + d] =  vb[(size_t)tk[r] * D_ + d];
    }
    __syncthreads();
    {
        int r = tid;
        float ss = 0.f;
#pragma unroll 8
        for (int d = 0; d < 64; d++) { float x = sk[r*PADK + d]; ss = fmaf(x, x, ss); }
        float inv = 1.f / fmaxf(sqrtf(ss), 1e-12f);
#pragma unroll 8
        for (int d = 0; d < 64; d++) sk[r*PADK + d] *= inv;
    }
    __syncthreads();

    int w = tid >> 5, lane = tid & 31;
    int rr = lane & 3, kk = lane >> 2;
    float* spw = sp + w * 16 * PADK;
    int rbase = w * 16 + rr;

    float m_[4], l_[4], oacc[4][8];
#pragma unroll
    for (int u = 0; u < 4; u++) {
        m_[u] = -INFINITY; l_[u] = 0.f;
#pragma unroll
        for (int v = 0; v < 8; v++) oacc[u][v] = 0.f;
    }
    int tqr[4], mqr[4];
#pragma unroll
    for (int u = 0; u < 4; u++) { tqr[u] = tq[rbase + 4*u]; mqr[u] = mq[rbase + 4*u]; }

    for (int tt = 0; tt < 4; tt++) {
        int jb = tt * 64;
        float dots[4][8];
#pragma unroll
        for (int u = 0; u < 4; u++)
#pragma unroll
            for (int s = 0; s < 8; s++) dots[u][s] = 0.f;

        for (int d = 0; d < 64; d++) {
            float qv[4];
#pragma unroll
            for (int u = 0; u < 4; u++) qv[u] = sq[(rbase + 4*u) * PADK + d];
#pragma unroll
            for (int s = 0; s < 8; s++) {
                float kv = sk[(jb + kk + 8*s) * PADK + d];
#pragma unroll
                for (int u = 0; u < 4; u++) dots[u][s] = fmaf(qv[u], kv, dots[u][s]);
            }
        }

        float tmax[4];
#pragma unroll
        for (int u = 0; u < 4; u++) {
            float mx = -INFINITY;
#pragma unroll
            for (int s = 0; s < 8; s++) {
                int j = jb + kk + 8*s;
                float val = dots[u][s] * 0.125f;
                if (!(mqr[u] && mk[j])) val = -1e9f;
                if (tqr[u] == tk[j])    val = -5e4f;
                dots[u][s] = val;
                mx = fmaxf(mx, val);
            }
            tmax[u] = mx;
        }
#pragma unroll
        for (int off = 4; off < 32; off <<= 1)
#pragma unroll
            for (int u = 0; u < 4; u++)
                tmax[u] = fmaxf(tmax[u], __shfl_xor_sync(0xffffffffu, tmax[u], off));

        float corr[4], lsum[4];
#pragma unroll
        for (int u = 0; u < 4; u++) {
            float mn = fmaxf(m_[u], tmax[u]);
            corr[u] = __expf(m_[u] - mn);
            m_[u] = mn;
            float sloc = 0.f;
#pragma unroll
            for (int s = 0; s < 8; s++) {
                float p = __expf(dots[u][s] - mn);
                dots[u][s] = p;
                sloc += p;
            }
            lsum[u] = sloc;
        }
#pragma unroll
        for (int off = 4; off < 32; off <<= 1)
#pragma unroll
            for (int u = 0; u < 4; u++)
                lsum[u] += __shfl_xor_sync(0xffffffffu, lsum[u], off);
#pragma unroll
        for (int u = 0; u < 4; u++) {
            l_[u] = l_[u] * corr[u] + lsum[u];
#pragma unroll
            for (int v = 0; v < 8; v++) oacc[u][v] *= corr[u];
#pragma unroll
            for (int s = 0; s < 8; s++) spw[(rr + 4*u) * PADK + kk + 8*s] = dots[u][s];
        }
        __syncwarp();

        for (int jl = 0; jl < 64; jl++) {
            float pv[4];
#pragma unroll
            for (int u = 0; u < 4; u++) pv[u] = spw[(rr + 4*u) * PADK + jl];
            float vvr[8];
#pragma unroll
            for (int v = 0; v < 8; v++) vvr[v] = sv[(jb + jl) * PADK + kk + 8*v];
#pragma unroll
            for (int u = 0; u < 4; u++)
#pragma unroll
                for (int v = 0; v < 8; v++)
                    oacc[u][v] = fmaf(pv[u], vvr[v], oacc[u][v]);
        }
        __syncwarp();
    }

#pragma unroll
    for (int u = 0; u < 4; u++) {
        int r  = rbase + 4*u;
        int gp = base + c * CL_ + r;
        float inv = 1.f / l_[u];
        if (kk == 0) g_slog[gp] = m_[u] + logf(l_[u]);
#pragma unroll
        for (int v = 0; v < 8; v++)
            g_so[(size_t)gp * D_ + kk + 8*v] = oacc[u][v] * inv;
    }
}

// ---------------- unsort + combine hash rounds ----------------
__global__ __launch_bounds__(256) void combine_kernel()
{
    int idx  = blockIdx.x * 256 + threadIdx.x;
    int d    = idx & 63;
    int rowi = idx >> 6;
    int t    = rowi & (T_-1);
    int bh   = rowi >> 12;
    int b = bh / H_, h = bh % H_;
    int p0 = g_undo[bh * TOTAL_ + t];
    int p1 = g_undo[bh * TOTAL_ + T_ + t];
    float l0 = g_slog[bh * TOTAL_ + p0];
    float l1 = g_slog[bh * TOTAL_ + p1];
    float mm = fmaxf(l0, l1);
    float w0 = __expf(l0 - mm), w1 = __expf(l1 - mm);
    float inv = 1.f / (w0 + w1);
    float o0 = g_so[((size_t)(bh * TOTAL_ + p0)) * D_ + d];
    float o1 = g_so[((size_t)(bh * TOTAL_ + p1)) * D_ + d];
    g_attn[((size_t)(b * T_ + t)) * HID_ + h * D_ + d] = (w0 * o0 + w1 * o1) * inv;
}

// ---------------- launcher ----------------
extern "C" void kernel_launch(void* const* d_in, const int* in_sizes, int n_in,
                              void* d_out, int out_size)
{
    const float* X    = (const float*)d_in[0];
    const float* mask = (const float*)d_in[1];
    const float* W_qk = (const float*)d_in[2];
    const float* W_v  = (const float*)d_in[3];
    const float* rot  = (const float*)d_in[4];
    const float* W_to = (const float*)d_in[5];
    const float* b_to = (const float*)d_in[6];
    const float* W_o  = (const float*)d_in[7];
    const float* b_o  = (const float*)d_in[8];
    float* out = (float*)d_out;

    cudaFuncSetAttribute(mma_gemm_kernel, cudaFuncAttributeMaxDynamicSharedMemorySize, GEMM_SMEM_MAX);
    cudaFuncSetAttribute(attn_kernel,     cudaFuncAttributeMaxDynamicSharedMemorySize, ATTN_SMEM_BYTES);

    const int NX4 = M_ * HID_ / 4;       // 3,145,728
    const int NW4 = HID_ * HID_ / 4;     // 147,456
    const int GX  = (NX4 + 255) / 256;
    const int GW  = (NW4 + 255) / 256;
    dim3 gg(HID_ / 128, M_ / 128);       // (6, 128)
    const int SM2 = 2 * 2 * 2 * SP_H * 2;   // 81920 (ns=2: 2 stages x 4 planes)
    const int SM3 = 2 * 3 * 2 * SP_H * 2;   // 122880 (ns=3: 2 stages x 6 planes)

    // --- QK projection: 3-way split (exact buckets) ---
    split_kernel<<<GX, 256>>>(X,    NX4, 3, 0, 0);
    split_kernel<<<GW, 256>>>(W_qk, NW4, 3, 1, 0);
    mma_gemm_kernel<<<gg, 256, SM3>>>(nullptr, nullptr, 1, 3);   // -> g_qk
    // --- V projection: 2-way split (A splits 0,1 of X reused) ---
    split_kernel<<<GW, 256>>>(W_v,  NW4, 2, 1, 0);
    mma_gemm_kernel<<<gg, 256, SM2>>>(nullptr, nullptr, 2, 2);   // -> g_v

    bucket_kernel<<<(BH_ * T_) / 8, 256>>>(rot);
    hist_kernel<<<BH_, 256>>>();
    scatter_kernel<<<dim3(NBTOT_, BH_), 256>>>();

    attn_kernel<<<dim3(NCH_, BH_), 256, ATTN_SMEM_BYTES>>>(mask);

    combine_kernel<<<(BH_ * T_ * D_) / 256, 256>>>();

    // --- W_to: 2-way split of attn output (device-resident, selected in-kernel) ---
    split_kernel<<<GX, 256>>>(nullptr, NX4, 2, 0, 1);
    split_kernel<<<GW, 256>>>(W_to,    NW4, 2, 1, 0);
    mma_gemm_kernel<<<gg, 256, SM2>>>(b_to, nullptr, 3, 2);      // -> g_tmp
    // --- W_o: 2-way split of tmp ---
    split_kernel<<<GX, 256>>>(nullptr, NX4, 2, 0, 2);
    split_kernel<<<GW, 256>>>(W_o,     NW4, 2, 1, 0);
    mma_gemm_kernel<<<gg, 256, SM2>>>(b_o, out, 0, 2);           // -> d_out
}

// round 12
// speedup vs baseline: 1.6248x; 1.6248x over previous
#include <cuda_runtime.h>
#include <cuda_bf16.h>
#include <cstdint>
#include <math.h>

#define B_      4
#define T_      4096
#define HID_    768
#define H_      12
#define D_      64
#define BH_     48
#define NBUCK_  32
#define NBTOT_  64
#define TOTAL_  8192
#define NCH_    64
#define CL_     128
#define M_      (B_*T_)      // 16384

// ---------------- scratch (static device globals; no allocation) ----------------
__device__ float g_qk[BH_*T_*D_];            // [bh][t][d]
__device__ float g_v [BH_*T_*D_];
__device__ int   g_bucket[BH_*TOTAL_];
__device__ int   g_sidx[BH_*TOTAL_];
__device__ int   g_undo[BH_*TOTAL_];
__device__ int   g_bbase[BH_*NBTOT_];
__device__ float g_so  [BH_*TOTAL_*D_];
__device__ float g_slog[BH_*TOTAL_];
__device__ float g_attn[M_*HID_];
__device__ float g_tmp [M_*HID_];
// bf16 split planes for GEMMs
__device__ __nv_bfloat16 g_as[3 * M_ * HID_];
__device__ __nv_bfloat16 g_bs[3 * HID_ * HID_];
// bf16 2-split planes for attention: [2][bh][t][64]
#define PQ_ ((size_t)BH_*T_*D_)
__device__ __nv_bfloat16 g_q16[2*BH_*T_*D_];
__device__ __nv_bfloat16 g_k16[2*BH_*T_*D_];   // normalized K
__device__ __nv_bfloat16 g_v16[2*BH_*T_*D_];

__device__ __forceinline__ unsigned int smem_u32(const void* p) {
    unsigned int a;
    asm("{ .reg .u64 t; cvta.to.shared.u64 t, %1; cvt.u32.u64 %0, t; }" : "=r"(a) : "l"(p));
    return a;
}
__device__ __forceinline__ void ldm_x4(unsigned int& r0, unsigned int& r1,
                                       unsigned int& r2, unsigned int& r3,
                                       unsigned int addr) {
    asm volatile("ldmatrix.sync.aligned.m8n8.x4.shared.b16 {%0,%1,%2,%3}, [%4];"
                 : "=r"(r0), "=r"(r1), "=r"(r2), "=r"(r3) : "r"(addr));
}
__device__ __forceinline__ void ldm_x4_t(unsigned int& r0, unsigned int& r1,
                                         unsigned int& r2, unsigned int& r3,
                                         unsigned int addr) {
    asm volatile("ldmatrix.sync.aligned.m8n8.x4.trans.shared.b16 {%0,%1,%2,%3}, [%4];"
                 : "=r"(r0), "=r"(r1), "=r"(r2), "=r"(r3) : "r"(addr));
}
__device__ __forceinline__ void mma_bf16(float& c0, float& c1, float& c2, float& c3,
                                         unsigned int a0, unsigned int a1,
                                         unsigned int a2, unsigned int a3,
                                         unsigned int b0, unsigned int b1) {
    asm volatile("mma.sync.aligned.m16n8k16.row.col.f32.bf16.bf16.f32 "
                 "{%0,%1,%2,%3}, {%4,%5,%6,%7}, {%8,%9}, {%0,%1,%2,%3};"
                 : "+f"(c0), "+f"(c1), "+f"(c2), "+f"(c3)
                 : "r"(a0), "r"(a1), "r"(a2), "r"(a3), "r"(b0), "r"(b1));
}
__device__ __forceinline__ unsigned int pack_bf16(float hi, float lo) {
    unsigned int r;
    asm("cvt.rn.bf16x2.f32 %0, %1, %2;" : "=r"(r) : "f"(hi), "f"(lo));
    return r;
}
__device__ __forceinline__ void cp8(unsigned int dst, const void* src) {
    asm volatile("cp.async.ca.shared.global [%0], [%1], 8;" :: "r"(dst), "l"(src));
}
__device__ __forceinline__ void cp_commit() {
    asm volatile("cp.async.commit_group;" ::: "memory");
}

// ---------------- fp32 -> ns bf16 split planes (for GEMMs) ----------------
__global__ __launch_bounds__(256) void split_kernel(const float* __restrict__ srcp,
                                                    int n4, int ns, int which, int insel)
{
    int idx = blockIdx.x * 256 + threadIdx.x;
    if (idx >= n4) return;
    const float* src = (insel == 0) ? srcp : (insel == 1 ? (const float*)g_attn : (const float*)g_tmp);
    float4 v = ((const float4*)src)[idx];
    __nv_bfloat16* dst = which ? g_bs : g_as;
    size_t stride = which ? (size_t)HID_ * HID_ : (size_t)M_ * HID_;
    float rx = v.x, ry = v.y, rz = v.z, rw = v.w;
    for (int s = 0; s < ns; s++) {
        __nv_bfloat16 bx = __float2bfloat16(rx), by = __float2bfloat16(ry);
        __nv_bfloat16 bz = __float2bfloat16(rz), bw = __float2bfloat16(rw);
        rx -= __bfloat162float(bx); ry -= __bfloat162float(by);
        rz -= __bfloat162float(bz); rw -= __bfloat162float(bw);
        uint2 u;
        u.x = (unsigned int)__bfloat16_as_ushort(bx) | ((unsigned int)__bfloat16_as_ushort(by) << 16);
        u.y = (unsigned int)__bfloat16_as_ushort(bz) | ((unsigned int)__bfloat16_as_ushort(bw) << 16);
        *(uint2*)(dst + s * stride + (size_t)idx * 4) = u;
    }
}

// ================= split-bf16 GEMM (R9 version: M128 N64 K32, 2-stage cp.async) ======
#define LDA_ 40
#define A_SP_H (128*LDA_)
#define B_SP_H (64*LDA_)
#define STAGE_H (3*A_SP_H + 3*B_SP_H)
#define STAGE_B (STAGE_H*2)
#define GEMM_SMEM_BYTES (2*STAGE_B)   // 92160

__global__ __launch_bounds__(256) void mma_gemm_kernel(
    const float* __restrict__ bias, float* __restrict__ Cout,
    int outmode, int ns)
{
    extern __shared__ char smem[];
    unsigned int sbase = smem_u32(smem);

    int tid = threadIdx.x, wid = tid >> 5, lane = tid & 31;
    int bm = blockIdx.y * 128, bn = blockIdx.x * 64;
    int wm = (wid & 3) * 32;
    int wn = (wid >> 2) * 32;

    const int np = (ns == 2) ? 3 : 6;
    const int PA[6] = {0, 0, 1, 1, 0, 2};
    const int PB[6] = {0, 1, 0, 1, 2, 0};

    float acc[2][4][4];
#pragma unroll
    for (int mi = 0; mi < 2; mi++)
#pragma unroll
        for (int ni = 0; ni < 4; ni++)
#pragma unroll
            for (int q = 0; q < 4; q++) acc[mi][ni][q] = 0.f;

    int arow = tid >> 3, aqc = tid & 7;
    int ra  = (lane & 7) + ((lane >> 3) & 1) * 8;
    int aco = (lane >> 4) * 8;
    unsigned int aoff[2];
#pragma unroll
    for (int mi = 0; mi < 2; mi++)
        aoff[mi] = (unsigned int)((wm + mi*16 + ra) * LDA_ + aco);
    int rb  = lane & 7;
    int bco = ((lane >> 3) & 1) * 8;
    unsigned int boff[2];
#pragma unroll
    for (int g = 0; g < 2; g++)
        boff[g] = (unsigned int)((wn + (g*2 + (lane >> 4))*8 + rb) * LDA_ + bco);

    const size_t ASZ = (size_t)M_ * HID_;
    const size_t BSZ = (size_t)HID_ * HID_;

    auto issue = [&](int kc, int buf) {
        int k0 = kc * 32;
        unsigned int sbuf = sbase + buf * STAGE_B;
        for (int s = 0; s < ns; s++) {
            const __nv_bfloat16* ga = g_as + s * ASZ + (size_t)(bm + arow) * HID_ + k0 + aqc * 4;
            unsigned int da = sbuf + (unsigned int)((s * A_SP_H + arow * LDA_ + aqc * 4) * 2);
#pragma unroll
            for (int i = 0; i < 4; i++)
                cp8(da + (unsigned int)(i * 32 * LDA_ * 2), ga + (size_t)i * 32 * HID_);
            const __nv_bfloat16* gb = g_bs + s * BSZ + (size_t)(bn + arow) * HID_ + k0 + aqc * 4;
            unsigned int db = sbuf + (unsigned int)((3 * A_SP_H + s * B_SP_H + arow * LDA_ + aqc * 4) * 2);
#pragma unroll
            for (int i = 0; i < 2; i++)
                cp8(db + (unsigned int)(i * 32 * LDA_ * 2), gb + (size_t)i * 32 * HID_);
        }
        cp_commit();
    };

    issue(0, 0);

    for (int kc = 0; kc < 24; kc++) {
        if (kc < 23) {
            issue(kc + 1, (kc + 1) & 1);
            asm volatile("cp.async.wait_group 1;" ::: "memory");
        } else {
            asm volatile("cp.async.wait_group 0;" ::: "memory");
        }
        __syncthreads();

        unsigned int sbuf = sbase + (kc & 1) * STAGE_B;
        for (int p = 0; p < np; p++) {
            unsigned int pa = sbuf + (unsigned int)(PA[p] * A_SP_H * 2);
            unsigned int pb = sbuf + (unsigned int)((3 * A_SP_H + PB[p] * B_SP_H) * 2);
#pragma unroll
            for (int k16 = 0; k16 < 2; k16++) {
                unsigned int kb = (unsigned int)(k16 * 16 * 2);
                unsigned int a[2][4], b[2][4];
#pragma unroll
                for (int mi = 0; mi < 2; mi++)
                    ldm_x4(a[mi][0], a[mi][1], a[mi][2], a[mi][3], pa + aoff[mi]*2 + kb);
#pragma unroll
                for (int g = 0; g < 2; g++)
                    ldm_x4(b[g][0], b[g][1], b[g][2], b[g][3], pb + boff[g]*2 + kb);
#pragma unroll
                for (int mi = 0; mi < 2; mi++) {
#pragma unroll
                    for (int ni = 0; ni < 4; ni++) {
                        unsigned int b0 = b[ni >> 1][(ni & 1) * 2];
                        unsigned int b1 = b[ni >> 1][(ni & 1) * 2 + 1];
                        mma_bf16(acc[mi][ni][0], acc[mi][ni][1], acc[mi][ni][2], acc[mi][ni][3],
                                 a[mi][0], a[mi][1], a[mi][2], a[mi][3], b0, b1);
                    }
                }
            }
        }
        __syncthreads();
    }

#pragma unroll
    for (int mi = 0; mi < 2; mi++) {
#pragma unroll
        for (int ni = 0; ni < 4; ni++) {
            int r0 = bm + wm + mi*16 + (lane >> 2);
            int cc = wn + ni*8 + (lane & 3)*2;
            float b0 = 0.f, b1 = 0.f;
            if (outmode == 0 || outmode == 3) { b0 = bias[bn+cc]; b1 = bias[bn+cc+1]; }
            float2 o0 = make_float2(acc[mi][ni][0] + b0, acc[mi][ni][1] + b1);
            float2 o1 = make_float2(acc[mi][ni][2] + b0, acc[mi][ni][3] + b1);
            if (outmode == 0 || outmode == 3) {
                float* dst = (outmode == 0) ? Cout : g_tmp;
                *(float2*)(dst + (size_t)r0     * HID_ + bn + cc) = o0;
                *(float2*)(dst + (size_t)(r0+8) * HID_ + bn + cc) = o1;
            } else {
                float* dst = (outmode == 1) ? g_qk : g_v;
                int h = bn >> 6;
                int b_0 = r0 >> 12, t_0 = r0 & (T_-1);
                int b_1 = (r0+8) >> 12, t_1 = (r0+8) & (T_-1);
                *(float2*)(dst + ((size_t)(b_0 * H_ + h) * T_ + t_0) * D_ + cc) = o0;
                *(float2*)(dst + ((size_t)(b_1 * H_ + h) * T_ + t_1) * D_ + cc) = o1;
            }
        }
    }
}

// ---------------- prep: normalize K + 2-split q/k/v to bf16 planes ----------------
__global__ __launch_bounds__(256) void prep16_kernel()
{
    int row = blockIdx.x * 8 + (threadIdx.x >> 5);   // bh*T + t
    int lane = threadIdx.x & 31;
    size_t off = (size_t)row * D_ + lane * 2;
    float2 q = *(const float2*)(g_qk + off);
    float ss = q.x*q.x + q.y*q.y;
#pragma unroll
    for (int o = 16; o > 0; o >>= 1) ss += __shfl_xor_sync(0xffffffffu, ss, o);
    float inv = 1.f / fmaxf(sqrtf(ss), 1e-12f);
    float2 v = *(const float2*)(g_v + off);
    float kx = q.x * inv, ky = q.y * inv;

    // q planes
    __nv_bfloat16 hx = __float2bfloat16(q.x), hy = __float2bfloat16(q.y);
    *(unsigned*)(g_q16 + off) = (unsigned)__bfloat16_as_ushort(hx) | ((unsigned)__bfloat16_as_ushort(hy) << 16);
    __nv_bfloat16 lx = __float2bfloat16(q.x - __bfloat162float(hx)),
                  ly = __float2bfloat16(q.y - __bfloat162float(hy));
    *(unsigned*)(g_q16 + PQ_ + off) = (unsigned)__bfloat16_as_ushort(lx) | ((unsigned)__bfloat16_as_ushort(ly) << 16);
    // k planes (normalized)
    hx = __float2bfloat16(kx); hy = __float2bfloat16(ky);
    *(unsigned*)(g_k16 + off) = (unsigned)__bfloat16_as_ushort(hx) | ((unsigned)__bfloat16_as_ushort(hy) << 16);
    lx = __float2bfloat16(kx - __bfloat162float(hx));
    ly = __float2bfloat16(ky - __bfloat162float(hy));
    *(unsigned*)(g_k16 + PQ_ + off) = (unsigned)__bfloat16_as_ushort(lx) | ((unsigned)__bfloat16_as_ushort(ly) << 16);
    // v planes
    hx = __float2bfloat16(v.x); hy = __float2bfloat16(v.y);
    *(unsigned*)(g_v16 + off) = (unsigned)__bfloat16_as_ushort(hx) | ((unsigned)__bfloat16_as_ushort(hy) << 16);
    lx = __float2bfloat16(v.x - __bfloat162float(hx));
    ly = __float2bfloat16(v.y - __bfloat162float(hy));
    *(unsigned*)(g_v16 + PQ_ + off) = (unsigned)__bfloat16_as_ushort(lx) | ((unsigned)__bfloat16_as_ushort(ly) << 16);
}

// ---------------- LSH bucketing ----------------
__global__ __launch_bounds__(256) void bucket_kernel(const float* __restrict__ rot)
{
    __shared__ float srot[D_ * 32];
    int tid = threadIdx.x;
    for (int i = tid; i < D_ * 32; i += 256) srot[i] = rot[i];
    __syncthreads();

    int lane = tid & 31;
    int wid  = tid >> 5;
    int row  = blockIdx.x * 8 + wid;
    int bh   = row >> 12;
    int t    = row & (T_-1);

    const float* q = g_qk + ((size_t)bh * T_ + t) * D_;
    float q0 = q[lane], q1 = q[lane + 32];
    float r = 0.f;
#pragma unroll
    for (int d = 0; d < 32; d++)
        r = fmaf(__shfl_sync(0xffffffffu, q0, d), srot[d * 32 + lane], r);
#pragma unroll
    for (int d = 0; d < 32; d++)
        r = fmaf(__shfl_sync(0xffffffffu, q1, d), srot[(d + 32) * 32 + lane], r);

    int i = lane & 15;
    float nr = -r;
    float v; int idx;
    if (r >= nr) { v = r;  idx = i; } else { v = nr; idx = i + 16; }
#pragma unroll
    for (int off = 8; off > 0; off >>= 1) {
        float ov = __shfl_down_sync(0xffffffffu, v,   off, 16);
        int   oi = __shfl_down_sync(0xffffffffu, idx, off, 16);
        if (ov > v || (ov == v && oi < idx)) { v = ov; idx = oi; }
    }
    if (i == 0) {
        int hash = lane >> 4;
        g_bucket[bh * TOTAL_ + hash * T_ + t] = idx + hash * NBUCK_;
    }
}

// ---------------- histogram + scan ----------------
__global__ __launch_bounds__(256) void hist_kernel()
{
    __shared__ int h[NBTOT_];
    int bh = blockIdx.x;
    int tid = threadIdx.x;
    if (tid < NBTOT_) h[tid] = 0;
    __syncthreads();
    const int* bp = g_bucket + bh * TOTAL_;
    for (int j = tid; j < TOTAL_; j += 256) atomicAdd(&h[bp[j]], 1);
    __syncthreads();
    if (tid == 0) {
        int run = 0;
        for (int b = 0; b < NBTOT_; b++) { g_bbase[bh * NBTOT_ + b] = run; run += h[b]; }
    }
}

// ---------------- stable scatter ----------------
__global__ __launch_bounds__(256) void scatter_kernel()
{
    int bh  = blockIdx.y;
    int myb = blockIdx.x;
    int tid = threadIdx.x;
    const int* bp = g_bucket + bh * TOTAL_;
    int j0 = tid * 32;
    int cnt = 0;
    for (int k = 0; k < 32; k++) cnt += (bp[j0 + k] == myb);

    __shared__ int s[256];
    s[tid] = cnt;
    __syncthreads();
    for (int off = 1; off < 256; off <<= 1) {
        int v = (tid >= off) ? s[tid - off] : 0;
        __syncthreads();
        s[tid] += v;
        __syncthreads();
    }
    int pos = g_bbase[bh * NBTOT_ + myb] + s[tid] - cnt;
    for (int k = 0; k < 32; k++) {
        int j = j0 + k;
        if (bp[j] == myb) {
            g_sidx[bh * TOTAL_ + pos] = j;
            g_undo[bh * TOTAL_ + j]   = pos;
            pos++;
        }
    }
}

// ================= FA2-style HMMA attention =================
// block = (chunk, bh); 256 threads, warp w owns q rows [w*16, w*16+16)
// kv = 256 (chunk + look-back), tiled 4x64 with online softmax
#define LDH 72
#define SQP (128*LDH)
#define SKP (256*LDH)
#define AT2_SMEM_B ((2*SQP + 4*SKP)*2 + (128+256+128+256)*4)   // 187392

__global__ __launch_bounds__(256, 1) void attn2_kernel(const float* __restrict__ mask)
{
    extern __shared__ __nv_bfloat16 sm16[];
    __nv_bfloat16* sqh = sm16;
    int* tq = (int*)(sm16 + 2*SQP + 4*SKP);
    int* tk = tq + 128;
    int* mq = tk + 256;
    int* mk = mq + 128;

    int c   = blockIdx.x;
    int bh  = blockIdx.y;
    int tid = threadIdx.x;
    int base = bh * TOTAL_;
    const float* mrow = mask + (bh / H_) * T_;

    if (tid < 128) {
        int si = g_sidx[base + c * CL_ + tid];
        int tp = si & (T_-1);
        tq[tid] = tp;
        mq[tid] = (mrow[tp] != 0.f);
    }
    {
        int j  = tid;
        int cp = (c + NCH_ - 1) & (NCH_ - 1);
        int spos = (j < CL_) ? (c * CL_ + j) : (cp * CL_ + (j - CL_));
        int si = g_sidx[base + spos];
        int tp = si & (T_-1);
        tk[j] = tp;
        mk[j] = (mrow[tp] != 0.f);
    }
    __syncthreads();

    size_t rbo = (size_t)bh * T_;
#pragma unroll
    for (int pl = 0; pl < 2; pl++) {
        __nv_bfloat16* dq = sqh + pl*SQP;
        const __nv_bfloat16* gq = g_q16 + pl*PQ_;
        for (int i = tid; i < 128*8; i += 256) {
            int r = i >> 3, ch = i & 7;
            *(uint4*)(dq + r*LDH + ch*8) = *(const uint4*)(gq + (rbo + tq[r])*D_ + ch*8);
        }
        __nv_bfloat16* dk = sqh + 2*SQP + pl*SKP;
        __nv_bfloat16* dv = sqh + 2*SQP + 2*SKP + pl*SKP;
        const __nv_bfloat16* gk = g_k16 + pl*PQ_;
        const __nv_bfloat16* gv = g_v16 + pl*PQ_;
        for (int i = tid; i < 256*8; i += 256) {
            int r = i >> 3, ch = i & 7;
            size_t go = (rbo + tk[r])*D_ + ch*8;
            *(uint4*)(dk + r*LDH + ch*8) = *(const uint4*)(gk + go);
            *(uint4*)(dv + r*LDH + ch*8) = *(const uint4*)(gv + go);
        }
    }
    __syncthreads();

    int w = tid >> 5, lane = tid & 31;
    unsigned sb16 = smem_u32(sm16);
    unsigned kbase = sb16 + 2*SQP*2;
    unsigned vbase = sb16 + (2*SQP + 2*SKP)*2;

    // Q fragments, cached (A-operand: rows w*16.., k = d)
    unsigned qh[4][4], ql[4][4];
    {
        unsigned aQ = ((unsigned)((w*16 + (lane&7) + ((lane>>3)&1)*8) * LDH + (lane>>4)*8)) * 2;
#pragma unroll
        for (int ks = 0; ks < 4; ks++) {
            ldm_x4(qh[ks][0], qh[ks][1], qh[ks][2], qh[ks][3], sb16 + aQ + ks*32);
            ldm_x4(ql[ks][0], ql[ks][1], ql[ks][2], ql[ks][3], sb16 + SQP*2 + aQ + ks*32);
        }
    }

    int g = lane >> 2;
    int qr0 = w*16 + g, qr1 = qr0 + 8;
    int tq0 = tq[qr0], tq1 = tq[qr1];
    int mq0 = mq[qr0], mq1 = mq[qr1];

    float m0 = -INFINITY, m1 = -INFINITY, l0 = 0.f, l1 = 0.f;
    float o[8][4];
#pragma unroll
    for (int j = 0; j < 8; j++)
#pragma unroll
        for (int q = 0; q < 4; q++) o[j][q] = 0.f;

    int krl = (lane>>4)*8 + (lane&7);          // K-frag row-in-16 (B pattern)
    int kcl = ((lane>>3)&1)*8;                 // K-frag col offset
    int vrl = (lane&7) + ((lane>>3)&1)*8;      // V-frag row-in-16 (trans pattern)
    int vcl = (lane>>4)*8;                     // V-frag col offset

    for (int tt = 0; tt < 4; tt++) {
        int jb = tt * 64;
        float cf[8][4];
#pragma unroll
        for (int j = 0; j < 8; j++)
#pragma unroll
            for (int q = 0; q < 4; q++) cf[j][q] = 0.f;

        // ---- QK^T: 3 passes (QhKh, QlKh, QhKl) ----
#pragma unroll
        for (int ks = 0; ks < 4; ks++) {
            unsigned kh[4][4], kl_[4][4];
#pragma unroll
            for (int gp = 0; gp < 4; gp++) {
                unsigned addr = kbase + ((unsigned)((jb + gp*16 + krl) * LDH + ks*16 + kcl) << 1);
                ldm_x4(kh[gp][0], kh[gp][1], kh[gp][2], kh[gp][3], addr);
                ldm_x4(kl_[gp][0], kl_[gp][1], kl_[gp][2], kl_[gp][3], addr + SKP*2);
            }
#pragma unroll
            for (int gp = 0; gp < 4; gp++) {
                mma_bf16(cf[2*gp][0], cf[2*gp][1], cf[2*gp][2], cf[2*gp][3],
                         qh[ks][0], qh[ks][1], qh[ks][2], qh[ks][3], kh[gp][0], kh[gp][1]);
                mma_bf16(cf[2*gp+1][0], cf[2*gp+1][1], cf[2*gp+1][2], cf[2*gp+1][3],
                         qh[ks][0], qh[ks][1], qh[ks][2], qh[ks][3], kh[gp][2], kh[gp][3]);
            }
#pragma unroll
            for (int gp = 0; gp < 4; gp++) {
                mma_bf16(cf[2*gp][0], cf[2*gp][1], cf[2*gp][2], cf[2*gp][3],
                         ql[ks][0], ql[ks][1], ql[ks][2], ql[ks][3], kh[gp][0], kh[gp][1]);
                mma_bf16(cf[2*gp+1][0], cf[2*gp+1][1], cf[2*gp+1][2], cf[2*gp+1][3],
                         ql[ks][0], ql[ks][1], ql[ks][2], ql[ks][3], kh[gp][2], kh[gp][3]);
            }
#pragma unroll
            for (int gp = 0; gp < 4; gp++) {
                mma_bf16(cf[2*gp][0], cf[2*gp][1], cf[2*gp][2], cf[2*gp][3],
                         qh[ks][0], qh[ks][1], qh[ks][2], qh[ks][3], kl_[gp][0], kl_[gp][1]);
                mma_bf16(cf[2*gp+1][0], cf[2*gp+1][1], cf[2*gp+1][2], cf[2*gp+1][3],
                         qh[ks][0], qh[ks][1], qh[ks][2], qh[ks][3], kl_[gp][2], kl_[gp][3]);
            }
        }

        // ---- scale + mask ----
        float mx0 = -INFINITY, mx1 = -INFINITY;
#pragma unroll
        for (int j = 0; j < 8; j++) {
            int col0 = jb + j*8 + (lane&3)*2;
            int t0 = tk[col0], t1 = tk[col0+1];
            int k0 = mk[col0], k1 = mk[col0+1];
            float v00 = cf[j][0]*0.125f, v01 = cf[j][1]*0.125f;
            float v10 = cf[j][2]*0.125f, v11 = cf[j][3]*0.125f;
            if (!(mq0 && k0)) v00 = -1e9f;
            if (!(mq0 && k1)) v01 = -1e9f;
            if (!(mq1 && k0)) v10 = -1e9f;
            if (!(mq1 && k1)) v11 = -1e9f;
            if (tq0 == t0) v00 = -5e4f;
            if (tq0 == t1) v01 = -5e4f;
            if (tq1 == t0) v10 = -5e4f;
            if (tq1 == t1) v11 = -5e4f;
            cf[j][0] = v00; cf[j][1] = v01; cf[j][2] = v10; cf[j][3] = v11;
            mx0 = fmaxf(mx0, fmaxf(v00, v01));
            mx1 = fmaxf(mx1, fmaxf(v10, v11));
        }
        mx0 = fmaxf(mx0, __shfl_xor_sync(0xffffffffu, mx0, 1));
        mx0 = fmaxf(mx0, __shfl_xor_sync(0xffffffffu, mx0, 2));
        mx1 = fmaxf(mx1, __shfl_xor_sync(0xffffffffu, mx1, 1));
        mx1 = fmaxf(mx1, __shfl_xor_sync(0xffffffffu, mx1, 2));

        float nm0 = fmaxf(m0, mx0), nm1 = fmaxf(m1, mx1);
        float corr0 = __expf(m0 - nm0), corr1 = __expf(m1 - nm1);
        m0 = nm0; m1 = nm1;
        l0 *= corr0; l1 *= corr1;
#pragma unroll
        for (int j = 0; j < 8; j++) {
            o[j][0] *= corr0; o[j][1] *= corr0;
            o[j][2] *= corr1; o[j][3] *= corr1;
        }
        float s0 = 0.f, s1 = 0.f;
#pragma unroll
        for (int j = 0; j < 8; j++) {
            cf[j][0] = __expf(cf[j][0] - m0); s0 += cf[j][0];
            cf[j][1] = __expf(cf[j][1] - m0); s0 += cf[j][1];
            cf[j][2] = __expf(cf[j][2] - m1); s1 += cf[j][2];
            cf[j][3] = __expf(cf[j][3] - m1); s1 += cf[j][3];
        }
        s0 += __shfl_xor_sync(0xffffffffu, s0, 1);
        s0 += __shfl_xor_sync(0xffffffffu, s0, 2);
        s1 += __shfl_xor_sync(0xffffffffu, s1, 1);
        s1 += __shfl_xor_sync(0xffffffffu, s1, 2);
        l0 += s0; l1 += s1;

        // ---- P·V: 3 passes (PhVh, PlVh, PhVl) ----
#pragma unroll
        for (int gp = 0; gp < 4; gp++) {
            // P fragments from C quads of kv-tiles 2gp, 2gp+1
            unsigned aPh[4], aPl[4];
#pragma unroll
            for (int half = 0; half < 2; half++) {
                int j = 2*gp + half;
                float p0 = cf[j][0], p1 = cf[j][1], p2 = cf[j][2], p3 = cf[j][3];
                aPh[0 + 2*half] = pack_bf16(p1, p0);
                aPh[1 + 2*half] = pack_bf16(p3, p2);
                float h0 = __bfloat162float(__float2bfloat16(p0));
                float h1 = __bfloat162float(__float2bfloat16(p1));
                float h2 = __bfloat162float(__float2bfloat16(p2));
                float h3 = __bfloat162float(__float2bfloat16(p3));
                aPl[0 + 2*half] = pack_bf16(p1 - h1, p0 - h0);
                aPl[1 + 2*half] = pack_bf16(p3 - h3, p2 - h2);
            }
            // fix ordering: aP[0]=rows g cols lo (tile 2gp), aP[1]=rows g+8 (tile 2gp),
            //               aP[2]=rows g cols hi (tile 2gp+1), aP[3]=rows g+8 (tile 2gp+1)
            // (half=0 -> indices 0,1 ; half=1 -> 2,3)  — matches A-frag layout.

            unsigned vh[4][4], vl[4][4];
#pragma unroll
            for (int gd = 0; gd < 4; gd++) {
                unsigned addr = vbase + ((unsigned)((jb + gp*16 + vrl) * LDH + gd*16 + vcl) << 1);
                ldm_x4_t(vh[gd][0], vh[gd][1], vh[gd][2], vh[gd][3], addr);
                ldm_x4_t(vl[gd][0], vl[gd][1], vl[gd][2], vl[gd][3], addr + SKP*2);
            }
#pragma unroll
            for (int gd = 0; gd < 4; gd++) {
                mma_bf16(o[2*gd][0], o[2*gd][1], o[2*gd][2], o[2*gd][3],
                         aPh[0], aPh[1], aPh[2], aPh[3], vh[gd][0], vh[gd][1]);
                mma_bf16(o[2*gd+1][0], o[2*gd+1][1], o[2*gd+1][2], o[2*gd+1][3],
                         aPh[0], aPh[1], aPh[2], aPh[3], vh[gd][2], vh[gd][3]);
            }
#pragma unroll
            for (int gd = 0; gd < 4; gd++) {
                mma_bf16(o[2*gd][0], o[2*gd][1], o[2*gd][2], o[2*gd][3],
                         aPl[0], aPl[1], aPl[2], aPl[3], vh[gd][0], vh[gd][1]);
                mma_bf16(o[2*gd+1][0], o[2*gd+1][1], o[2*gd+1][2], o[2*gd+1][3],
                         aPl[0], aPl[1], aPl[2], aPl[3], vh[gd][2], vh[gd][3]);
            }
#pragma unroll
            for (int gd = 0; gd < 4; gd++) {
                mma_bf16(o[2*gd][0], o[2*gd][1], o[2*gd][2], o[2*gd][3],
                         aPh[0], aPh[1], aPh[2], aPh[3], vl[gd][0], vl[gd][1]);
                mma_bf16(o[2*gd+1][0], o[2*gd+1][1], o[2*gd+1][2], o[2*gd+1][3],
                         aPh[0], aPh[1], aPh[2], aPh[3], vl[gd][2], vl[gd][3]);
            }
        }
    }

    // ---- epilogue ----
    float inv0 = 1.f / l0, inv1 = 1.f / l1;
    int go0 = base + c * CL_ + qr0;
    int go1 = base + c * CL_ + qr1;
    if ((lane & 3) == 0) {
        g_slog[go0] = m0 + logf(l0);
        g_slog[go1] = m1 + logf(l1);
    }
#pragma unroll
    for (int j = 0; j < 8; j++) {
        int col = j*8 + (lane&3)*2;
        *(float2*)(g_so + (size_t)go0 * D_ + col) = make_float2(o[j][0]*inv0, o[j][1]*inv0);
        *(float2*)(g_so + (size_t)go1 * D_ + col) = make_float2(o[j][2]*inv1, o[j][3]*inv1);
    }
}

// ---------------- unsort + combine hash rounds ----------------
__global__ __launch_bounds__(256) void combine_kernel()
{
    int idx  = blockIdx.x * 256 + threadIdx.x;
    int d    = idx & 63;
    int rowi = idx >> 6;
    int t    = rowi & (T_-1);
    int bh   = rowi >> 12;
    int b = bh / H_, h = bh % H_;
    int p0 = g_undo[bh * TOTAL_ + t];
    int p1 = g_undo[bh * TOTAL_ + T_ + t];
    float l0 = g_slog[bh * TOTAL_ + p0];
    float l1 = g_slog[bh * TOTAL_ + p1];
    float mm = fmaxf(l0, l1);
    float w0 = __expf(l0 - mm), w1 = __expf(l1 - mm);
    float inv = 1.f / (w0 + w1);
    float o0 = g_so[((size_t)(bh * TOTAL_ + p0)) * D_ + d];
    float o1 = g_so[((size_t)(bh * TOTAL_ + p1)) * D_ + d];
    g_attn[((size_t)(b * T_ + t)) * HID_ + h * D_ + d] = (w0 * o0 + w1 * o1) * inv;
}

// ---------------- launcher ----------------
extern "C" void kernel_launch(void* const* d_in, const int* in_sizes, int n_in,
                              void* d_out, int out_size)
{
    const float* X    = (const float*)d_in[0];
    const float* mask = (const float*)d_in[1];
    const float* W_qk = (const float*)d_in[2];
    const float* W_v  = (const float*)d_in[3];
    const float* rot  = (const float*)d_in[4];
    const float* W_to = (const float*)d_in[5];
    const float* b_to = (const float*)d_in[6];
    const float* W_o  = (const float*)d_in[7];
    const float* b_o  = (const float*)d_in[8];
    float* out = (float*)d_out;

    cudaFuncSetAttribute(mma_gemm_kernel, cudaFuncAttributeMaxDynamicSharedMemorySize, GEMM_SMEM_BYTES);
    cudaFuncSetAttribute(attn2_kernel,    cudaFuncAttributeMaxDynamicSharedMemorySize, AT2_SMEM_B);

    const int NX4 = M_ * HID_ / 4;
    const int NW4 = HID_ * HID_ / 4;
    const int GX  = (NX4 + 255) / 256;
    const int GW  = (NW4 + 255) / 256;
    dim3 gg(HID_ / 64, M_ / 128);   // (12, 128)

    // QK projection: 3-way split (exact buckets); V: 2-way
    split_kernel<<<GX, 256>>>(X,    NX4, 3, 0, 0);
    split_kernel<<<GW, 256>>>(W_qk, NW4, 3, 1, 0);
    mma_gemm_kernel<<<gg, 256, GEMM_SMEM_BYTES>>>(nullptr, nullptr, 1, 3);   // -> g_qk
    split_kernel<<<GW, 256>>>(W_v,  NW4, 2, 1, 0);
    mma_gemm_kernel<<<gg, 256, GEMM_SMEM_BYTES>>>(nullptr, nullptr, 2, 2);   // -> g_v

    prep16_kernel<<<(BH_ * T_) / 8, 256>>>();
    bucket_kernel<<<(BH_ * T_) / 8, 256>>>(rot);
    hist_kernel<<<BH_, 256>>>();
    scatter_kernel<<<dim3(NBTOT_, BH_), 256>>>();

    attn2_kernel<<<dim3(NCH_, BH_), 256, AT2_SMEM_B>>>(mask);

    combine_kernel<<<(BH_ * T_ * D_) / 256, 256>>>();

    split_kernel<<<GX, 256>>>(nullptr, NX4, 2, 0, 1);
    split_kernel<<<GW, 256>>>(W_to,    NW4, 2, 1, 0);
    mma_gemm_kernel<<<gg, 256, GEMM_SMEM_BYTES>>>(b_to, nullptr, 3, 2);      // -> g_tmp
    split_kernel<<<GX, 256>>>(nullptr, NX4, 2, 0, 2);
    split_kernel<<<GW, 256>>>(W_o,     NW4, 2, 1, 0);
    mma_gemm_kernel<<<gg, 256, GEMM_SMEM_BYTES>>>(b_o, out, 0, 2);           // -> d_out
}

// round 13
// speedup vs baseline: 1.6711x; 1.0285x over previous
#include <cuda_runtime.h>
#include <cuda_bf16.h>
#include <cstdint>
#include <math.h>

#define B_      4
#define T_      4096
#define HID_    768
#define H_      12
#define D_      64
#define BH_     48
#define NBUCK_  32
#define NBTOT_  64
#define TOTAL_  8192
#define NCH_    64
#define CL_     128
#define M_      (B_*T_)      // 16384

// ---------------- scratch (static device globals; no allocation) ----------------
__device__ float g_qk[BH_*T_*D_];            // [bh][t][d]
__device__ float g_v [BH_*T_*D_];
__device__ int   g_bucket[BH_*TOTAL_];
__device__ int   g_sidx[BH_*TOTAL_];
__device__ int   g_undo[BH_*TOTAL_];
__device__ int   g_bbase[BH_*NBTOT_];
__device__ float g_so  [BH_*TOTAL_*D_];
__device__ float g_slog[BH_*TOTAL_];
// combined output weight path
__device__ float g_wtt[HID_*HID_];           // W_to^T
__device__ float g_wc [HID_*HID_];           // W_o @ W_to
__device__ float g_bc [HID_];                // b_o + W_o @ b_to
// bf16 split planes for GEMMs
__device__ __nv_bfloat16 g_as[3 * M_ * HID_];
__device__ __nv_bfloat16 g_bs[3 * HID_ * HID_];
// bf16 2-split planes for attention: [2][bh][t][64]
#define PQ_ ((size_t)BH_*T_*D_)
__device__ __nv_bfloat16 g_q16[2*BH_*T_*D_];
__device__ __nv_bfloat16 g_k16[2*BH_*T_*D_];   // normalized K
__device__ __nv_bfloat16 g_v16[2*BH_*T_*D_];

__device__ __forceinline__ unsigned int smem_u32(const void* p) {
    unsigned int a;
    asm("{ .reg .u64 t; cvta.to.shared.u64 t, %1; cvt.u32.u64 %0, t; }" : "=r"(a) : "l"(p));
    return a;
}
__device__ __forceinline__ void ldm_x4(unsigned int& r0, unsigned int& r1,
                                       unsigned int& r2, unsigned int& r3,
                                       unsigned int addr) {
    asm volatile("ldmatrix.sync.aligned.m8n8.x4.shared.b16 {%0,%1,%2,%3}, [%4];"
                 : "=r"(r0), "=r"(r1), "=r"(r2), "=r"(r3) : "r"(addr));
}
__device__ __forceinline__ void ldm_x4_t(unsigned int& r0, unsigned int& r1,
                                         unsigned int& r2, unsigned int& r3,
                                         unsigned int addr) {
    asm volatile("ldmatrix.sync.aligned.m8n8.x4.trans.shared.b16 {%0,%1,%2,%3}, [%4];"
                 : "=r"(r0), "=r"(r1), "=r"(r2), "=r"(r3) : "r"(addr));
}
__device__ __forceinline__ void mma_bf16(float& c0, float& c1, float& c2, float& c3,
                                         unsigned int a0, unsigned int a1,
                                         unsigned int a2, unsigned int a3,
                                         unsigned int b0, unsigned int b1) {
    asm volatile("mma.sync.aligned.m16n8k16.row.col.f32.bf16.bf16.f32 "
                 "{%0,%1,%2,%3}, {%4,%5,%6,%7}, {%8,%9}, {%0,%1,%2,%3};"
                 : "+f"(c0), "+f"(c1), "+f"(c2), "+f"(c3)
                 : "r"(a0), "r"(a1), "r"(a2), "r"(a3), "r"(b0), "r"(b1));
}
__device__ __forceinline__ unsigned int pack_bf16(float hi, float lo) {
    unsigned int r;
    asm("cvt.rn.bf16x2.f32 %0, %1, %2;" : "=r"(r) : "f"(hi), "f"(lo));
    return r;
}
__device__ __forceinline__ void cp8(unsigned int dst, const void* src) {
    asm volatile("cp.async.ca.shared.global [%0], [%1], 8;" :: "r"(dst), "l"(src));
}
__device__ __forceinline__ void cp_commit() {
    asm volatile("cp.async.commit_group;" ::: "memory");
}

// ---------------- fp32 -> ns bf16 split planes (for GEMMs) ----------------
// which: 0 -> g_as, 1 -> g_bs     insel: 0 -> src param, 3 -> g_wc
__global__ __launch_bounds__(256) void split_kernel(const float* __restrict__ srcp,
                                                    int n4, int ns, int which, int insel)
{
    int idx = blockIdx.x * 256 + threadIdx.x;
    if (idx >= n4) return;
    const float* src = (insel == 0) ? srcp : (const float*)g_wc;
    float4 v = ((const float4*)src)[idx];
    __nv_bfloat16* dst = which ? g_bs : g_as;
    size_t stride = which ? (size_t)HID_ * HID_ : (size_t)M_ * HID_;
    float rx = v.x, ry = v.y, rz = v.z, rw = v.w;
    for (int s = 0; s < ns; s++) {
        __nv_bfloat16 bx = __float2bfloat16(rx), by = __float2bfloat16(ry);
        __nv_bfloat16 bz = __float2bfloat16(rz), bw = __float2bfloat16(rw);
        rx -= __bfloat162float(bx); ry -= __bfloat162float(by);
        rz -= __bfloat162float(bz); rw -= __bfloat162float(bw);
        uint2 u;
        u.x = (unsigned int)__bfloat16_as_ushort(bx) | ((unsigned int)__bfloat16_as_ushort(by) << 16);
        u.y = (unsigned int)__bfloat16_as_ushort(bz) | ((unsigned int)__bfloat16_as_ushort(bw) << 16);
        *(uint2*)(dst + s * stride + (size_t)idx * 4) = u;
    }
}

// ---------------- transpose W_to -> g_wtt ----------------
__global__ __launch_bounds__(256) void transpose768_kernel(const float* __restrict__ src)
{
    int idx = blockIdx.x * 256 + threadIdx.x;      // output linear index
    if (idx >= HID_ * HID_) return;
    int j = idx % HID_, n = idx / HID_;
    g_wtt[idx] = src[j * HID_ + n];                // g_wtt[n][j] = W_to[j][n]
}

// ---------------- fp32 SGEMM 768x768x768 (R3-proven structure): g_wc = W_o @ W_to ----
// C[m,n] = sum_k A[m,k] * g_wtt[n,k]
__global__ __launch_bounds__(256) void sgemm768_kernel(const float* __restrict__ A)
{
    __shared__ float As[16][128];
    __shared__ float Ws[16][64];
    const int K = HID_;
    int bm = blockIdx.y * 128;
    int bn = blockIdx.x * 64;
    int tid = threadIdx.x;
    int tx = tid & 15, ty = tid >> 4;

    float acc[8][4];
#pragma unroll
    for (int i = 0; i < 8; i++)
#pragma unroll
        for (int j = 0; j < 4; j++) acc[i][j] = 0.f;

    for (int k0 = 0; k0 < K; k0 += 16) {
#pragma unroll
        for (int li = 0; li < 2; li++) {
            int i   = tid + li * 256;
            int row = i >> 2;
            int kq  = (i & 3) << 2;
            float4 av = *(const float4*)(A + (size_t)(bm + row) * K + k0 + kq);
            As[kq+0][row] = av.x; As[kq+1][row] = av.y;
            As[kq+2][row] = av.z; As[kq+3][row] = av.w;
        }
        {
            int row = tid >> 2;
            int kq  = (tid & 3) << 2;
            float4 wv = *(const float4*)(g_wtt + (size_t)(bn + row) * K + k0 + kq);
            Ws[kq+0][row] = wv.x; Ws[kq+1][row] = wv.y;
            Ws[kq+2][row] = wv.z; Ws[kq+3][row] = wv.w;
        }
        __syncthreads();
#pragma unroll
        for (int kk = 0; kk < 16; kk++) {
            float4 a0 = *(const float4*)&As[kk][ty*8];
            float4 a1 = *(const float4*)&As[kk][ty*8 + 4];
            float4 bv = *(const float4*)&Ws[kk][tx*4];
            float a[8] = {a0.x,a0.y,a0.z,a0.w,a1.x,a1.y,a1.z,a1.w};
            float b[4] = {bv.x,bv.y,bv.z,bv.w};
#pragma unroll
            for (int i = 0; i < 8; i++)
#pragma unroll
                for (int j = 0; j < 4; j++)
                    acc[i][j] = fmaf(a[i], b[j], acc[i][j]);
        }
        __syncthreads();
    }

    int col = bn + tx * 4;
#pragma unroll
    for (int i = 0; i < 8; i++) {
        int row = bm + ty * 8 + i;
        *(float4*)(g_wc + (size_t)row * HID_ + col) =
            make_float4(acc[i][0], acc[i][1], acc[i][2], acc[i][3]);
    }
}

// ---------------- combined bias: g_bc = b_o + W_o @ b_to ----------------
__global__ __launch_bounds__(256) void biascomb_kernel(const float* __restrict__ b_to,
                                                       const float* __restrict__ b_o,
                                                       const float* __restrict__ W_o)
{
    int i = blockIdx.x * 256 + threadIdx.x;
    if (i >= HID_) return;
    float s = b_o[i];
    for (int k = 0; k < HID_; k++) s = fmaf(W_o[(size_t)i * HID_ + k], b_to[k], s);
    g_bc[i] = s;
}

// ================= split-bf16 GEMM (M128 N64 K32, 2-stage cp.async) ======
#define LDA_ 40
#define A_SP_H (128*LDA_)
#define B_SP_H (64*LDA_)
#define STAGE_H (3*A_SP_H + 3*B_SP_H)
#define STAGE_B (STAGE_H*2)
#define GEMM_SMEM_BYTES (2*STAGE_B)   // 92160

// outmode: 1=g_qk merged-head, 2=g_v merged-head, 4=Cout + g_bc bias
__global__ __launch_bounds__(256) void mma_gemm_kernel(
    float* __restrict__ Cout, int outmode, int ns)
{
    extern __shared__ char smem[];
    unsigned int sbase = smem_u32(smem);

    int tid = threadIdx.x, wid = tid >> 5, lane = tid & 31;
    int bm = blockIdx.y * 128, bn = blockIdx.x * 64;
    int wm = (wid & 3) * 32;
    int wn = (wid >> 2) * 32;

    const int np = (ns == 2) ? 3 : 6;
    const int PA[6] = {0, 0, 1, 1, 0, 2};
    const int PB[6] = {0, 1, 0, 1, 2, 0};

    float acc[2][4][4];
#pragma unroll
    for (int mi = 0; mi < 2; mi++)
#pragma unroll
        for (int ni = 0; ni < 4; ni++)
#pragma unroll
            for (int q = 0; q < 4; q++) acc[mi][ni][q] = 0.f;

    int arow = tid >> 3, aqc = tid & 7;
    int ra  = (lane & 7) + ((lane >> 3) & 1) * 8;
    int aco = (lane >> 4) * 8;
    unsigned int aoff[2];
#pragma unroll
    for (int mi = 0; mi < 2; mi++)
        aoff[mi] = (unsigned int)((wm + mi*16 + ra) * LDA_ + aco);
    int rb  = lane & 7;
    int bco = ((lane >> 3) & 1) * 8;
    unsigned int boff[2];
#pragma unroll
    for (int g = 0; g < 2; g++)
        boff[g] = (unsigned int)((wn + (g*2 + (lane >> 4))*8 + rb) * LDA_ + bco);

    const size_t ASZ = (size_t)M_ * HID_;
    const size_t BSZ = (size_t)HID_ * HID_;

    auto issue = [&](int kc, int buf) {
        int k0 = kc * 32;
        unsigned int sbuf = sbase + buf * STAGE_B;
        for (int s = 0; s < ns; s++) {
            const __nv_bfloat16* ga = g_as + s * ASZ + (size_t)(bm + arow) * HID_ + k0 + aqc * 4;
            unsigned int da = sbuf + (unsigned int)((s * A_SP_H + arow * LDA_ + aqc * 4) * 2);
#pragma unroll
            for (int i = 0; i < 4; i++)
                cp8(da + (unsigned int)(i * 32 * LDA_ * 2), ga + (size_t)i * 32 * HID_);
            const __nv_bfloat16* gb = g_bs + s * BSZ + (size_t)(bn + arow) * HID_ + k0 + aqc * 4;
            unsigned int db = sbuf + (unsigned int)((3 * A_SP_H + s * B_SP_H + arow * LDA_ + aqc * 4) * 2);
#pragma unroll
            for (int i = 0; i < 2; i++)
                cp8(db + (unsigned int)(i * 32 * LDA_ * 2), gb + (size_t)i * 32 * HID_);
        }
        cp_commit();
    };

    issue(0, 0);

    for (int kc = 0; kc < 24; kc++) {
        if (kc < 23) {
            issue(kc + 1, (kc + 1) & 1);
            asm volatile("cp.async.wait_group 1;" ::: "memory");
        } else {
            asm volatile("cp.async.wait_group 0;" ::: "memory");
        }
        __syncthreads();

        unsigned int sbuf = sbase + (kc & 1) * STAGE_B;
        for (int p = 0; p < np; p++) {
            unsigned int pa = sbuf + (unsigned int)(PA[p] * A_SP_H * 2);
            unsigned int pb = sbuf + (unsigned int)((3 * A_SP_H + PB[p] * B_SP_H) * 2);
#pragma unroll
            for (int k16 = 0; k16 < 2; k16++) {
                unsigned int kb = (unsigned int)(k16 * 16 * 2);
                unsigned int a[2][4], b[2][4];
#pragma unroll
                for (int mi = 0; mi < 2; mi++)
                    ldm_x4(a[mi][0], a[mi][1], a[mi][2], a[mi][3], pa + aoff[mi]*2 + kb);
#pragma unroll
                for (int g = 0; g < 2; g++)
                    ldm_x4(b[g][0], b[g][1], b[g][2], b[g][3], pb + boff[g]*2 + kb);
#pragma unroll
                for (int mi = 0; mi < 2; mi++) {
#pragma unroll
                    for (int ni = 0; ni < 4; ni++) {
                        unsigned int b0 = b[ni >> 1][(ni & 1) * 2];
                        unsigned int b1 = b[ni >> 1][(ni & 1) * 2 + 1];
                        mma_bf16(acc[mi][ni][0], acc[mi][ni][1], acc[mi][ni][2], acc[mi][ni][3],
                                 a[mi][0], a[mi][1], a[mi][2], a[mi][3], b0, b1);
                    }
                }
            }
        }
        __syncthreads();
    }

#pragma unroll
    for (int mi = 0; mi < 2; mi++) {
#pragma unroll
        for (int ni = 0; ni < 4; ni++) {
            int r0 = bm + wm + mi*16 + (lane >> 2);
            int cc = wn + ni*8 + (lane & 3)*2;
            if (outmode == 4) {
                float b0 = g_bc[bn+cc], b1 = g_bc[bn+cc+1];
                *(float2*)(Cout + (size_t)r0     * HID_ + bn + cc) =
                    make_float2(acc[mi][ni][0] + b0, acc[mi][ni][1] + b1);
                *(float2*)(Cout + (size_t)(r0+8) * HID_ + bn + cc) =
                    make_float2(acc[mi][ni][2] + b0, acc[mi][ni][3] + b1);
            } else {
                float* dst = (outmode == 1) ? g_qk : g_v;
                int h = bn >> 6;
                int b_0 = r0 >> 12, t_0 = r0 & (T_-1);
                int b_1 = (r0+8) >> 12, t_1 = (r0+8) & (T_-1);
                *(float2*)(dst + ((size_t)(b_0 * H_ + h) * T_ + t_0) * D_ + cc) =
                    make_float2(acc[mi][ni][0], acc[mi][ni][1]);
                *(float2*)(dst + ((size_t)(b_1 * H_ + h) * T_ + t_1) * D_ + cc) =
                    make_float2(acc[mi][ni][2], acc[mi][ni][3]);
            }
        }
    }
}

// ---------------- prep: normalize K + 2-split q/k/v to bf16 planes ----------------
__global__ __launch_bounds__(256) void prep16_kernel()
{
    int row = blockIdx.x * 8 + (threadIdx.x >> 5);   // bh*T + t
    int lane = threadIdx.x & 31;
    size_t off = (size_t)row * D_ + lane * 2;
    float2 q = *(const float2*)(g_qk + off);
    float ss = q.x*q.x + q.y*q.y;
#pragma unroll
    for (int o = 16; o > 0; o >>= 1) ss += __shfl_xor_sync(0xffffffffu, ss, o);
    float inv = 1.f / fmaxf(sqrtf(ss), 1e-12f);
    float2 v = *(const float2*)(g_v + off);
    float kx = q.x * inv, ky = q.y * inv;

    __nv_bfloat16 hx = __float2bfloat16(q.x), hy = __float2bfloat16(q.y);
    *(unsigned*)(g_q16 + off) = (unsigned)__bfloat16_as_ushort(hx) | ((unsigned)__bfloat16_as_ushort(hy) << 16);
    __nv_bfloat16 lx = __float2bfloat16(q.x - __bfloat162float(hx)),
                  ly = __float2bfloat16(q.y - __bfloat162float(hy));
    *(unsigned*)(g_q16 + PQ_ + off) = (unsigned)__bfloat16_as_ushort(lx) | ((unsigned)__bfloat16_as_ushort(ly) << 16);
    hx = __float2bfloat16(kx); hy = __float2bfloat16(ky);
    *(unsigned*)(g_k16 + off) = (unsigned)__bfloat16_as_ushort(hx) | ((unsigned)__bfloat16_as_ushort(hy) << 16);
    lx = __float2bfloat16(kx - __bfloat162float(hx));
    ly = __float2bfloat16(ky - __bfloat162float(hy));
    *(unsigned*)(g_k16 + PQ_ + off) = (unsigned)__bfloat16_as_ushort(lx) | ((unsigned)__bfloat16_as_ushort(ly) << 16);
    hx = __float2bfloat16(v.x); hy = __float2bfloat16(v.y);
    *(unsigned*)(g_v16 + off) = (unsigned)__bfloat16_as_ushort(hx) | ((unsigned)__bfloat16_as_ushort(hy) << 16);
    lx = __float2bfloat16(v.x - __bfloat162float(hx));
    ly = __float2bfloat16(v.y - __bfloat162float(hy));
    *(unsigned*)(g_v16 + PQ_ + off) = (unsigned)__bfloat16_as_ushort(lx) | ((unsigned)__bfloat16_as_ushort(ly) << 16);
}

// ---------------- LSH bucketing ----------------
__global__ __launch_bounds__(256) void bucket_kernel(const float* __restrict__ rot)
{
    __shared__ float srot[D_ * 32];
    int tid = threadIdx.x;
    for (int i = tid; i < D_ * 32; i += 256) srot[i] = rot[i];
    __syncthreads();

    int lane = tid & 31;
    int wid  = tid >> 5;
    int row  = blockIdx.x * 8 + wid;
    int bh   = row >> 12;
    int t    = row & (T_-1);

    const float* q = g_qk + ((size_t)bh * T_ + t) * D_;
    float q0 = q[lane], q1 = q[lane + 32];
    float r = 0.f;
#pragma unroll
    for (int d = 0; d < 32; d++)
        r = fmaf(__shfl_sync(0xffffffffu, q0, d), srot[d * 32 + lane], r);
#pragma unroll
    for (int d = 0; d < 32; d++)
        r = fmaf(__shfl_sync(0xffffffffu, q1, d), srot[(d + 32) * 32 + lane], r);

    int i = lane & 15;
    float nr = -r;
    float v; int idx;
    if (r >= nr) { v = r;  idx = i; } else { v = nr; idx = i + 16; }
#pragma unroll
    for (int off = 8; off > 0; off >>= 1) {
        float ov = __shfl_down_sync(0xffffffffu, v,   off, 16);
        int   oi = __shfl_down_sync(0xffffffffu, idx, off, 16);
        if (ov > v || (ov == v && oi < idx)) { v = ov; idx = oi; }
    }
    if (i == 0) {
        int hash = lane >> 4;
        g_bucket[bh * TOTAL_ + hash * T_ + t] = idx + hash * NBUCK_;
    }
}

// ---------------- histogram + scan ----------------
__global__ __launch_bounds__(256) void hist_kernel()
{
    __shared__ int h[NBTOT_];
    int bh = blockIdx.x;
    int tid = threadIdx.x;
    if (tid < NBTOT_) h[tid] = 0;
    __syncthreads();
    const int* bp = g_bucket + bh * TOTAL_;
    for (int j = tid; j < TOTAL_; j += 256) atomicAdd(&h[bp[j]], 1);
    __syncthreads();
    if (tid == 0) {
        int run = 0;
        for (int b = 0; b < NBTOT_; b++) { g_bbase[bh * NBTOT_ + b] = run; run += h[b]; }
    }
}

// ---------------- stable scatter ----------------
__global__ __launch_bounds__(256) void scatter_kernel()
{
    int bh  = blockIdx.y;
    int myb = blockIdx.x;
    int tid = threadIdx.x;
    const int* bp = g_bucket + bh * TOTAL_;
    int j0 = tid * 32;
    int cnt = 0;
    for (int k = 0; k < 32; k++) cnt += (bp[j0 + k] == myb);

    __shared__ int s[256];
    s[tid] = cnt;
    __syncthreads();
    for (int off = 1; off < 256; off <<= 1) {
        int v = (tid >= off) ? s[tid - off] : 0;
        __syncthreads();
        s[tid] += v;
        __syncthreads();
    }
    int pos = g_bbase[bh * NBTOT_ + myb] + s[tid] - cnt;
    for (int k = 0; k < 32; k++) {
        int j = j0 + k;
        if (bp[j] == myb) {
            g_sidx[bh * TOTAL_ + pos] = j;
            g_undo[bh * TOTAL_ + j]   = pos;
            pos++;
        }
    }
}

// ================= FA2-style HMMA attention =================
#define LDH 72
#define SQP (128*LDH)
#define SKP (256*LDH)
#define AT2_SMEM_B ((2*SQP + 4*SKP)*2 + (128+256+128+256)*4)   // 187392

__global__ __launch_bounds__(256, 1) void attn2_kernel(const float* __restrict__ mask)
{
    extern __shared__ __nv_bfloat16 sm16[];
    __nv_bfloat16* sqh = sm16;
    int* tq = (int*)(sm16 + 2*SQP + 4*SKP);
    int* tk = tq + 128;
    int* mq = tk + 256;
    int* mk = mq + 128;

    int c   = blockIdx.x;
    int bh  = blockIdx.y;
    int tid = threadIdx.x;
    int base = bh * TOTAL_;
    const float* mrow = mask + (bh / H_) * T_;

    if (tid < 128) {
        int si = g_sidx[base + c * CL_ + tid];
        int tp = si & (T_-1);
        tq[tid] = tp;
        mq[tid] = (mrow[tp] != 0.f);
    }
    {
        int j  = tid;
        int cp = (c + NCH_ - 1) & (NCH_ - 1);
        int spos = (j < CL_) ? (c * CL_ + j) : (cp * CL_ + (j - CL_));
        int si = g_sidx[base + spos];
        int tp = si & (T_-1);
        tk[j] = tp;
        mk[j] = (mrow[tp] != 0.f);
    }
    __syncthreads();

    size_t rbo = (size_t)bh * T_;
#pragma unroll
    for (int pl = 0; pl < 2; pl++) {
        __nv_bfloat16* dq = sqh + pl*SQP;
        const __nv_bfloat16* gq = g_q16 + pl*PQ_;
        for (int i = tid; i < 128*8; i += 256) {
            int r = i >> 3, ch = i & 7;
            *(uint4*)(dq + r*LDH + ch*8) = *(const uint4*)(gq + (rbo + tq[r])*D_ + ch*8);
        }
        __nv_bfloat16* dk = sqh + 2*SQP + pl*SKP;
        __nv_bfloat16* dv = sqh + 2*SQP + 2*SKP + pl*SKP;
        const __nv_bfloat16* gk = g_k16 + pl*PQ_;
        const __nv_bfloat16* gv = g_v16 + pl*PQ_;
        for (int i = tid; i < 256*8; i += 256) {
            int r = i >> 3, ch = i & 7;
            size_t go = (rbo + tk[r])*D_ + ch*8;
            *(uint4*)(dk + r*LDH + ch*8) = *(const uint4*)(gk + go);
            *(uint4*)(dv + r*LDH + ch*8) = *(const uint4*)(gv + go);
        }
    }
    __syncthreads();

    int w = tid >> 5, lane = tid & 31;
    unsigned sb16 = smem_u32(sm16);
    unsigned kbase = sb16 + 2*SQP*2;
    unsigned vbase = sb16 + (2*SQP + 2*SKP)*2;

    unsigned qh[4][4], ql[4][4];
    {
        unsigned aQ = ((unsigned)((w*16 + (lane&7) + ((lane>>3)&1)*8) * LDH + (lane>>4)*8)) * 2;
#pragma unroll
        for (int ks = 0; ks < 4; ks++) {
            ldm_x4(qh[ks][0], qh[ks][1], qh[ks][2], qh[ks][3], sb16 + aQ + ks*32);
            ldm_x4(ql[ks][0], ql[ks][1], ql[ks][2], ql[ks][3], sb16 + SQP*2 + aQ + ks*32);
        }
    }

    int g = lane >> 2;
    int qr0 = w*16 + g, qr1 = qr0 + 8;
    int tq0 = tq[qr0], tq1 = tq[qr1];
    int mq0 = mq[qr0], mq1 = mq[qr1];

    float m0 = -INFINITY, m1 = -INFINITY, l0 = 0.f, l1 = 0.f;
    float o[8][4];
#pragma unroll
    for (int j = 0; j < 8; j++)
#pragma unroll
        for (int q = 0; q < 4; q++) o[j][q] = 0.f;

    int krl = (lane>>4)*8 + (lane&7);
    int kcl = ((lane>>3)&1)*8;
    int vrl = (lane&7) + ((lane>>3)&1)*8;
    int vcl = (lane>>4)*8;

    for (int tt = 0; tt < 4; tt++) {
        int jb = tt * 64;
        float cf[8][4];
#pragma unroll
        for (int j = 0; j < 8; j++)
#pragma unroll
            for (int q = 0; q < 4; q++) cf[j][q] = 0.f;

#pragma unroll
        for (int ks = 0; ks < 4; ks++) {
            unsigned kh[4][4], kl_[4][4];
#pragma unroll
            for (int gp = 0; gp < 4; gp++) {
                unsigned addr = kbase + ((unsigned)((jb + gp*16 + krl) * LDH + ks*16 + kcl) << 1);
                ldm_x4(kh[gp][0], kh[gp][1], kh[gp][2], kh[gp][3], addr);
                ldm_x4(kl_[gp][0], kl_[gp][1], kl_[gp][2], kl_[gp][3], addr + SKP*2);
            }
#pragma unroll
            for (int gp = 0; gp < 4; gp++) {
                mma_bf16(cf[2*gp][0], cf[2*gp][1], cf[2*gp][2], cf[2*gp][3],
                         qh[ks][0], qh[ks][1], qh[ks][2], qh[ks][3], kh[gp][0], kh[gp][1]);
                mma_bf16(cf[2*gp+1][0], cf[2*gp+1][1], cf[2*gp+1][2], cf[2*gp+1][3],
                         qh[ks][0], qh[ks][1], qh[ks][2], qh[ks][3], kh[gp][2], kh[gp][3]);
            }
#pragma unroll
            for (int gp = 0; gp < 4; gp++) {
                mma_bf16(cf[2*gp][0], cf[2*gp][1], cf[2*gp][2], cf[2*gp][3],
                         ql[ks][0], ql[ks][1], ql[ks][2], ql[ks][3], kh[gp][0], kh[gp][1]);
                mma_bf16(cf[2*gp+1][0], cf[2*gp+1][1], cf[2*gp+1][2], cf[2*gp+1][3],
                         ql[ks][0], ql[ks][1], ql[ks][2], ql[ks][3], kh[gp][2], kh[gp][3]);
            }
#pragma unroll
            for (int gp = 0; gp < 4; gp++) {
                mma_bf16(cf[2*gp][0], cf[2*gp][1], cf[2*gp][2], cf[2*gp][3],
                         qh[ks][0], qh[ks][1], qh[ks][2], qh[ks][3], kl_[gp][0], kl_[gp][1]);
                mma_bf16(cf[2*gp+1][0], cf[2*gp+1][1], cf[2*gp+1][2], cf[2*gp+1][3],
                         qh[ks][0], qh[ks][1], qh[ks][2], qh[ks][3], kl_[gp][2], kl_[gp][3]);
            }
        }

        float mx0 = -INFINITY, mx1 = -INFINITY;
#pragma unroll
        for (int j = 0; j < 8; j++) {
            int col0 = jb + j*8 + (lane&3)*2;
            int t0 = tk[col0], t1 = tk[col0+1];
            int k0 = mk[col0], k1 = mk[col0+1];
            float v00 = cf[j][0]*0.125f, v01 = cf[j][1]*0.125f;
            float v10 = cf[j][2]*0.125f, v11 = cf[j][3]*0.125f;
            if (!(mq0 && k0)) v00 = -1e9f;
            if (!(mq0 && k1)) v01 = -1e9f;
            if (!(mq1 && k0)) v10 = -1e9f;
            if (!(mq1 && k1)) v11 = -1e9f;
            if (tq0 == t0) v00 = -5e4f;
            if (tq0 == t1) v01 = -5e4f;
            if (tq1 == t0) v10 = -5e4f;
            if (tq1 == t1) v11 = -5e4f;
            cf[j][0] = v00; cf[j][1] = v01; cf[j][2] = v10; cf[j][3] = v11;
            mx0 = fmaxf(mx0, fmaxf(v00, v01));
            mx1 = fmaxf(mx1, fmaxf(v10, v11));
        }
        mx0 = fmaxf(mx0, __shfl_xor_sync(0xffffffffu, mx0, 1));
        mx0 = fmaxf(mx0, __shfl_xor_sync(0xffffffffu, mx0, 2));
        mx1 = fmaxf(mx1, __shfl_xor_sync(0xffffffffu, mx1, 1));
        mx1 = fmaxf(mx1, __shfl_xor_sync(0xffffffffu, mx1, 2));

        float nm0 = fmaxf(m0, mx0), nm1 = fmaxf(m1, mx1);
        float corr0 = __expf(m0 - nm0), corr1 = __expf(m1 - nm1);
        m0 = nm0; m1 = nm1;
        l0 *= corr0; l1 *= corr1;
#pragma unroll
        for (int j = 0; j < 8; j++) {
            o[j][0] *= corr0; o[j][1] *= corr0;
            o[j][2] *= corr1; o[j][3] *= corr1;
        }
        float s0 = 0.f, s1 = 0.f;
#pragma unroll
        for (int j = 0; j < 8; j++) {
            cf[j][0] = __expf(cf[j][0] - m0); s0 += cf[j][0];
            cf[j][1] = __expf(cf[j][1] - m0); s0 += cf[j][1];
            cf[j][2] = __expf(cf[j][2] - m1); s1 += cf[j][2];
            cf[j][3] = __expf(cf[j][3] - m1); s1 += cf[j][3];
        }
        s0 += __shfl_xor_sync(0xffffffffu, s0, 1);
        s0 += __shfl_xor_sync(0xffffffffu, s0, 2);
        s1 += __shfl_xor_sync(0xffffffffu, s1, 1);
        s1 += __shfl_xor_sync(0xffffffffu, s1, 2);
        l0 += s0; l1 += s1;

#pragma unroll
        for (int gp = 0; gp < 4; gp++) {
            unsigned aPh[4], aPl[4];
#pragma unroll
            for (int half = 0; half < 2; half++) {
                int j = 2*gp + half;
                float p0 = cf[j][0], p1 = cf[j][1], p2 = cf[j][2], p3 = cf[j][3];
                aPh[0 + 2*half] = pack_bf16(p1, p0);
                aPh[1 + 2*half] = pack_bf16(p3, p2);
                float h0 = __bfloat162float(__float2bfloat16(p0));
                float h1 = __bfloat162float(__float2bfloat16(p1));
                float h2 = __bfloat162float(__float2bfloat16(p2));
                float h3 = __bfloat162float(__float2bfloat16(p3));
                aPl[0 + 2*half] = pack_bf16(p1 - h1, p0 - h0);
                aPl[1 + 2*half] = pack_bf16(p3 - h3, p2 - h2);
            }

            unsigned vh[4][4], vl[4][4];
#pragma unroll
            for (int gd = 0; gd < 4; gd++) {
                unsigned addr = vbase + ((unsigned)((jb + gp*16 + vrl) * LDH + gd*16 + vcl) << 1);
                ldm_x4_t(vh[gd][0], vh[gd][1], vh[gd][2], vh[gd][3], addr);
                ldm_x4_t(vl[gd][0], vl[gd][1], vl[gd][2], vl[gd][3], addr + SKP*2);
            }
#pragma unroll
            for (int gd = 0; gd < 4; gd++) {
                mma_bf16(o[2*gd][0], o[2*gd][1], o[2*gd][2], o[2*gd][3],
                         aPh[0], aPh[1], aPh[2], aPh[3], vh[gd][0], vh[gd][1]);
                mma_bf16(o[2*gd+1][0], o[2*gd+1][1], o[2*gd+1][2], o[2*gd+1][3],
                         aPh[0], aPh[1], aPh[2], aPh[3], vh[gd][2], vh[gd][3]);
            }
#pragma unroll
            for (int gd = 0; gd < 4; gd++) {
                mma_bf16(o[2*gd][0], o[2*gd][1], o[2*gd][2], o[2*gd][3],
                         aPl[0], aPl[1], aPl[2], aPl[3], vh[gd][0], vh[gd][1]);
                mma_bf16(o[2*gd+1][0], o[2*gd+1][1], o[2*gd+1][2], o[2*gd+1][3],
                         aPl[0], aPl[1], aPl[2], aPl[3], vh[gd][2], vh[gd][3]);
            }
#pragma unroll
            for (int gd = 0; gd < 4; gd++) {
                mma_bf16(o[2*gd][0], o[2*gd][1], o[2*gd][2], o[2*gd][3],
                         aPh[0], aPh[1], aPh[2], aPh[3], vl[gd][0], vl[gd][1]);
                mma_bf16(o[2*gd+1][0], o[2*gd+1][1], o[2*gd+1][2], o[2*gd+1][3],
                         aPh[0], aPh[1], aPh[2], aPh[3], vl[gd][2], vl[gd][3]);
            }
        }
    }

    float inv0 = 1.f / l0, inv1 = 1.f / l1;
    int go0 = base + c * CL_ + qr0;
    int go1 = base + c * CL_ + qr1;
    if ((lane & 3) == 0) {
        g_slog[go0] = m0 + logf(l0);
        g_slog[go1] = m1 + logf(l1);
    }
#pragma unroll
    for (int j = 0; j < 8; j++) {
        int col = j*8 + (lane&3)*2;
        *(float2*)(g_so + (size_t)go0 * D_ + col) = make_float2(o[j][0]*inv0, o[j][1]*inv0);
        *(float2*)(g_so + (size_t)go1 * D_ + col) = make_float2(o[j][2]*inv1, o[j][3]*inv1);
    }
}

// ---------------- unsort + combine hash rounds (fused 2-way bf16 split) ----------------
__global__ __launch_bounds__(256) void combine_kernel()
{
    int idx  = blockIdx.x * 256 + threadIdx.x;
    int d    = idx & 63;
    int rowi = idx >> 6;
    int t    = rowi & (T_-1);
    int bh   = rowi >> 12;
    int b = bh / H_, h = bh % H_;
    int p0 = g_undo[bh * TOTAL_ + t];
    int p1 = g_undo[bh * TOTAL_ + T_ + t];
    float l0 = g_slog[bh * TOTAL_ + p0];
    float l1 = g_slog[bh * TOTAL_ + p1];
    float mm = fmaxf(l0, l1);
    float w0 = __expf(l0 - mm), w1 = __expf(l1 - mm);
    float inv = 1.f / (w0 + w1);
    float o0 = g_so[((size_t)(bh * TOTAL_ + p0)) * D_ + d];
    float o1 = g_so[((size_t)(bh * TOTAL_ + p1)) * D_ + d];
    float val = (w0 * o0 + w1 * o1) * inv;
    size_t oidx = ((size_t)(b * T_ + t)) * HID_ + h * D_ + d;
    __nv_bfloat16 hi = __float2bfloat16(val);
    g_as[oidx] = hi;
    g_as[(size_t)M_ * HID_ + oidx] = __float2bfloat16(val - __bfloat162float(hi));
}

// ---------------- launcher ----------------
extern "C" void kernel_launch(void* const* d_in, const int* in_sizes, int n_in,
                              void* d_out, int out_size)
{
    const float* X    = (const float*)d_in[0];
    const float* mask = (const float*)d_in[1];
    const float* W_qk = (const float*)d_in[2];
    const float* W_v  = (const float*)d_in[3];
    const float* rot  = (const float*)d_in[4];
    const float* W_to = (const float*)d_in[5];
    const float* b_to = (const float*)d_in[6];
    const float* W_o  = (const float*)d_in[7];
    const float* b_o  = (const float*)d_in[8];
    float* out = (float*)d_out;

    cudaFuncSetAttribute(mma_gemm_kernel, cudaFuncAttributeMaxDynamicSharedMemorySize, GEMM_SMEM_BYTES);
    cudaFuncSetAttribute(attn2_kernel,    cudaFuncAttributeMaxDynamicSharedMemorySize, AT2_SMEM_B);

    const int NX4 = M_ * HID_ / 4;
    const int NW4 = HID_ * HID_ / 4;
    const int GX  = (NX4 + 255) / 256;
    const int GW  = (NW4 + 255) / 256;
    dim3 gg(HID_ / 64, M_ / 128);   // (12, 128)

    // QK projection: 3-way split (exact buckets); V: 2-way
    split_kernel<<<GX, 256>>>(X,    NX4, 3, 0, 0);
    split_kernel<<<GW, 256>>>(W_qk, NW4, 3, 1, 0);
    mma_gemm_kernel<<<gg, 256, GEMM_SMEM_BYTES>>>(nullptr, 1, 3);   // -> g_qk
    split_kernel<<<GW, 256>>>(W_v,  NW4, 2, 1, 0);
    mma_gemm_kernel<<<gg, 256, GEMM_SMEM_BYTES>>>(nullptr, 2, 2);   // -> g_v

    prep16_kernel<<<(BH_ * T_) / 8, 256>>>();
    bucket_kernel<<<(BH_ * T_) / 8, 256>>>(rot);
    hist_kernel<<<BH_, 256>>>();
    scatter_kernel<<<dim3(NBTOT_, BH_), 256>>>();

    attn2_kernel<<<dim3(NCH_, BH_), 256, AT2_SMEM_B>>>(mask);

    combine_kernel<<<(BH_ * T_ * D_) / 256, 256>>>();   // -> g_as planes (fused split)

    // combined output weight: W_c = W_o @ W_to, b_c = b_o + W_o @ b_to
    transpose768_kernel<<<(HID_*HID_ + 255)/256, 256>>>(W_to);
    sgemm768_kernel<<<dim3(HID_/64, HID_/128), 256>>>(W_o);
    biascomb_kernel<<<(HID_ + 255)/256, 256>>>(b_to, b_o, W_o);
    split_kernel<<<GW, 256>>>(nullptr, NW4, 2, 1, 3);               // g_wc -> g_bs

    mma_gemm_kernel<<<gg, 256, GEMM_SMEM_BYTES>>>(out, 4, 2);       // -> d_out
}

// round 14
// speedup vs baseline: 1.6974x; 1.0157x over previous
#include <cuda_runtime.h>
#include <cuda_bf16.h>
#include <cstdint>
#include <math.h>

#define B_      4
#define T_      4096
#define HID_    768
#define H_      12
#define D_      64
#define BH_     48
#define NBUCK_  32
#define NBTOT_  64
#define TOTAL_  8192
#define NCH_    64
#define CL_     128
#define M_      (B_*T_)      // 16384

// ---------------- scratch (static device globals; no allocation) ----------------
__device__ float g_qk[BH_*T_*D_];            // [bh][t][d]
__device__ int   g_bucket[BH_*TOTAL_];
__device__ int   g_sidx[BH_*TOTAL_];
__device__ int   g_undo[BH_*TOTAL_];
__device__ int   g_bbase[BH_*NBTOT_];
__device__ float g_so  [BH_*TOTAL_*D_];
__device__ float g_slog[BH_*TOTAL_];
// combined output weight path
__device__ float g_wtt[HID_*HID_];           // W_to^T
__device__ float g_wc [HID_*HID_];           // W_o @ W_to
__device__ float g_bc [HID_];                // b_o + W_o @ b_to
// bf16 split planes for GEMMs
__device__ __nv_bfloat16 g_as[3 * M_ * HID_];
__device__ __nv_bfloat16 g_bs[3 * HID_ * HID_];
// bf16 2-split planes for attention: [2][bh][t][64]
#define PQ_ ((size_t)BH_*T_*D_)
__device__ __nv_bfloat16 g_q16[2*BH_*T_*D_];
__device__ __nv_bfloat16 g_k16[2*BH_*T_*D_];   // normalized K
__device__ __nv_bfloat16 g_v16[2*BH_*T_*D_];

__device__ __forceinline__ unsigned int smem_u32(const void* p) {
    unsigned int a;
    asm("{ .reg .u64 t; cvta.to.shared.u64 t, %1; cvt.u32.u64 %0, t; }" : "=r"(a) : "l"(p));
    return a;
}
__device__ __forceinline__ void ldm_x4(unsigned int& r0, unsigned int& r1,
                                       unsigned int& r2, unsigned int& r3,
                                       unsigned int addr) {
    asm volatile("ldmatrix.sync.aligned.m8n8.x4.shared.b16 {%0,%1,%2,%3}, [%4];"
                 : "=r"(r0), "=r"(r1), "=r"(r2), "=r"(r3) : "r"(addr));
}
__device__ __forceinline__ void ldm_x4_t(unsigned int& r0, unsigned int& r1,
                                         unsigned int& r2, unsigned int& r3,
                                         unsigned int addr) {
    asm volatile("ldmatrix.sync.aligned.m8n8.x4.trans.shared.b16 {%0,%1,%2,%3}, [%4];"
                 : "=r"(r0), "=r"(r1), "=r"(r2), "=r"(r3) : "r"(addr));
}
__device__ __forceinline__ void mma_bf16(float& c0, float& c1, float& c2, float& c3,
                                         unsigned int a0, unsigned int a1,
                                         unsigned int a2, unsigned int a3,
                                         unsigned int b0, unsigned int b1) {
    asm volatile("mma.sync.aligned.m16n8k16.row.col.f32.bf16.bf16.f32 "
                 "{%0,%1,%2,%3}, {%4,%5,%6,%7}, {%8,%9}, {%0,%1,%2,%3};"
                 : "+f"(c0), "+f"(c1), "+f"(c2), "+f"(c3)
                 : "r"(a0), "r"(a1), "r"(a2), "r"(a3), "r"(b0), "r"(b1));
}
__device__ __forceinline__ unsigned int pack_bf16(float hi, float lo) {
    unsigned int r;
    asm("cvt.rn.bf16x2.f32 %0, %1, %2;" : "=r"(r) : "f"(hi), "f"(lo));
    return r;
}
__device__ __forceinline__ void cp8(unsigned int dst, const void* src) {
    asm volatile("cp.async.ca.shared.global [%0], [%1], 8;" :: "r"(dst), "l"(src));
}
__device__ __forceinline__ void cp_commit() {
    asm volatile("cp.async.commit_group;" ::: "memory");
}
__device__ __forceinline__ unsigned int split2_u32(float a, float b, int pl) {
    __nv_bfloat16 ha = __float2bfloat16(a), hb = __float2bfloat16(b);
    if (pl == 0)
        return (unsigned int)__bfloat16_as_ushort(ha) | ((unsigned int)__bfloat16_as_ushort(hb) << 16);
    __nv_bfloat16 la = __float2bfloat16(a - __bfloat162float(ha));
    __nv_bfloat16 lb = __float2bfloat16(b - __bfloat162float(hb));
    return (unsigned int)__bfloat16_as_ushort(la) | ((unsigned int)__bfloat16_as_ushort(lb) << 16);
}

// ---------------- fp32 -> ns bf16 split planes (for GEMMs) ----------------
// which: 0 -> g_as, 1 -> g_bs     insel: 0 -> src param, 3 -> g_wc
__global__ __launch_bounds__(256) void split_kernel(const float* __restrict__ srcp,
                                                    int n4, int ns, int which, int insel)
{
    int idx = blockIdx.x * 256 + threadIdx.x;
    if (idx >= n4) return;
    const float* src = (insel == 0) ? srcp : (const float*)g_wc;
    float4 v = ((const float4*)src)[idx];
    __nv_bfloat16* dst = which ? g_bs : g_as;
    size_t stride = which ? (size_t)HID_ * HID_ : (size_t)M_ * HID_;
    float rx = v.x, ry = v.y, rz = v.z, rw = v.w;
    for (int s = 0; s < ns; s++) {
        __nv_bfloat16 bx = __float2bfloat16(rx), by = __float2bfloat16(ry);
        __nv_bfloat16 bz = __float2bfloat16(rz), bw = __float2bfloat16(rw);
        rx -= __bfloat162float(bx); ry -= __bfloat162float(by);
        rz -= __bfloat162float(bz); rw -= __bfloat162float(bw);
        uint2 u;
        u.x = (unsigned int)__bfloat16_as_ushort(bx) | ((unsigned int)__bfloat16_as_ushort(by) << 16);
        u.y = (unsigned int)__bfloat16_as_ushort(bz) | ((unsigned int)__bfloat16_as_ushort(bw) << 16);
        *(uint2*)(dst + s * stride + (size_t)idx * 4) = u;
    }
}

// ---------------- transpose W_to -> g_wtt ----------------
__global__ __launch_bounds__(256) void transpose768_kernel(const float* __restrict__ src)
{
    int idx = blockIdx.x * 256 + threadIdx.x;
    if (idx >= HID_ * HID_) return;
    int j = idx % HID_, n = idx / HID_;
    g_wtt[idx] = src[j * HID_ + n];
}

// ---------------- fp32 SGEMM 768x768x768: g_wc = W_o @ W_to ----------------
__global__ __launch_bounds__(256) void sgemm768_kernel(const float* __restrict__ A)
{
    __shared__ float As[16][128];
    __shared__ float Ws[16][64];
    const int K = HID_;
    int bm = blockIdx.y * 128;
    int bn = blockIdx.x * 64;
    int tid = threadIdx.x;
    int tx = tid & 15, ty = tid >> 4;

    float acc[8][4];
#pragma unroll
    for (int i = 0; i < 8; i++)
#pragma unroll
        for (int j = 0; j < 4; j++) acc[i][j] = 0.f;

    for (int k0 = 0; k0 < K; k0 += 16) {
#pragma unroll
        for (int li = 0; li < 2; li++) {
            int i   = tid + li * 256;
            int row = i >> 2;
            int kq  = (i & 3) << 2;
            float4 av = *(const float4*)(A + (size_t)(bm + row) * K + k0 + kq);
            As[kq+0][row] = av.x; As[kq+1][row] = av.y;
            As[kq+2][row] = av.z; As[kq+3][row] = av.w;
        }
        {
            int row = tid >> 2;
            int kq  = (tid & 3) << 2;
            float4 wv = *(const float4*)(g_wtt + (size_t)(bn + row) * K + k0 + kq);
            Ws[kq+0][row] = wv.x; Ws[kq+1][row] = wv.y;
            Ws[kq+2][row] = wv.z; Ws[kq+3][row] = wv.w;
        }
        __syncthreads();
#pragma unroll
        for (int kk = 0; kk < 16; kk++) {
            float4 a0 = *(const float4*)&As[kk][ty*8];
            float4 a1 = *(const float4*)&As[kk][ty*8 + 4];
            float4 bv = *(const float4*)&Ws[kk][tx*4];
            float a[8] = {a0.x,a0.y,a0.z,a0.w,a1.x,a1.y,a1.z,a1.w};
            float b[4] = {bv.x,bv.y,bv.z,bv.w};
#pragma unroll
            for (int i = 0; i < 8; i++)
#pragma unroll
                for (int j = 0; j < 4; j++)
                    acc[i][j] = fmaf(a[i], b[j], acc[i][j]);
        }
        __syncthreads();
    }

    int col = bn + tx * 4;
#pragma unroll
    for (int i = 0; i < 8; i++) {
        int row = bm + ty * 8 + i;
        *(float4*)(g_wc + (size_t)row * HID_ + col) =
            make_float4(acc[i][0], acc[i][1], acc[i][2], acc[i][3]);
    }
}

// ---------------- combined bias: g_bc = b_o + W_o @ b_to ----------------
__global__ __launch_bounds__(256) void biascomb_kernel(const float* __restrict__ b_to,
                                                       const float* __restrict__ b_o,
                                                       const float* __restrict__ W_o)
{
    int i = blockIdx.x * 256 + threadIdx.x;
    if (i >= HID_) return;
    float s = b_o[i];
    for (int k = 0; k < HID_; k++) s = fmaf(W_o[(size_t)i * HID_ + k], b_to[k], s);
    g_bc[i] = s;
}

// ================= split-bf16 GEMM (M128 N64 K32, 2-stage cp.async) ======
#define LDA_ 40
#define A_SP_H (128*LDA_)
#define B_SP_H (64*LDA_)
#define STAGE3_B ((3*A_SP_H + 3*B_SP_H)*2)   // 46080
#define STAGE2_B ((2*A_SP_H + 2*B_SP_H)*2)   // 30720
#define GEMM_SMEM_MAX (2*STAGE3_B)           // 92160

// outmode: 1=g_qk merged-head, 2=g_v16 split planes merged-head, 4=Cout + g_bc bias
__global__ __launch_bounds__(256) void mma_gemm_kernel(
    float* __restrict__ Cout, int outmode, int ns)
{
    extern __shared__ char smem[];
    unsigned int sbase = smem_u32(smem);

    int tid = threadIdx.x, wid = tid >> 5, lane = tid & 31;
    int bm = blockIdx.y * 128, bn = blockIdx.x * 64;
    int wm = (wid & 3) * 32;
    int wn = (wid >> 2) * 32;

    const int np = (ns == 2) ? 3 : 6;
    const int PA[6] = {0, 0, 1, 1, 0, 2};
    const int PB[6] = {0, 1, 0, 1, 2, 0};
    const unsigned int stage_b = (ns == 2) ? STAGE2_B : STAGE3_B;
    const unsigned int b_off   = (unsigned int)(ns * A_SP_H * 2);  // B planes after ns A planes

    float acc[2][4][4];
#pragma unroll
    for (int mi = 0; mi < 2; mi++)
#pragma unroll
        for (int ni = 0; ni < 4; ni++)
#pragma unroll
            for (int q = 0; q < 4; q++) acc[mi][ni][q] = 0.f;

    int arow = tid >> 3, aqc = tid & 7;
    int ra  = (lane & 7) + ((lane >> 3) & 1) * 8;
    int aco = (lane >> 4) * 8;
    unsigned int aoff[2];
#pragma unroll
    for (int mi = 0; mi < 2; mi++)
        aoff[mi] = (unsigned int)((wm + mi*16 + ra) * LDA_ + aco);
    int rb  = lane & 7;
    int bco = ((lane >> 3) & 1) * 8;
    unsigned int boff[2];
#pragma unroll
    for (int g = 0; g < 2; g++)
        boff[g] = (unsigned int)((wn + (g*2 + (lane >> 4))*8 + rb) * LDA_ + bco);

    const size_t ASZ = (size_t)M_ * HID_;
    const size_t BSZ = (size_t)HID_ * HID_;

    auto issue = [&](int kc, int buf) {
        int k0 = kc * 32;
        unsigned int sbuf = sbase + buf * stage_b;
        for (int s = 0; s < ns; s++) {
            const __nv_bfloat16* ga = g_as + s * ASZ + (size_t)(bm + arow) * HID_ + k0 + aqc * 4;
            unsigned int da = sbuf + (unsigned int)((s * A_SP_H + arow * LDA_ + aqc * 4) * 2);
#pragma unroll
            for (int i = 0; i < 4; i++)
                cp8(da + (unsigned int)(i * 32 * LDA_ * 2), ga + (size_t)i * 32 * HID_);
            const __nv_bfloat16* gb = g_bs + s * BSZ + (size_t)(bn + arow) * HID_ + k0 + aqc * 4;
            unsigned int db = sbuf + b_off + (unsigned int)((s * B_SP_H + arow * LDA_ + aqc * 4) * 2);
#pragma unroll
            for (int i = 0; i < 2; i++)
                cp8(db + (unsigned int)(i * 32 * LDA_ * 2), gb + (size_t)i * 32 * HID_);
        }
        cp_commit();
    };

    issue(0, 0);

    for (int kc = 0; kc < 24; kc++) {
        if (kc < 23) {
            issue(kc + 1, (kc + 1) & 1);
            asm volatile("cp.async.wait_group 1;" ::: "memory");
        } else {
            asm volatile("cp.async.wait_group 0;" ::: "memory");
        }
        __syncthreads();

        unsigned int sbuf = sbase + (kc & 1) * stage_b;
        for (int p = 0; p < np; p++) {
            unsigned int pa = sbuf + (unsigned int)(PA[p] * A_SP_H * 2);
            unsigned int pb = sbuf + b_off + (unsigned int)(PB[p] * B_SP_H * 2);
#pragma unroll
            for (int k16 = 0; k16 < 2; k16++) {
                unsigned int kb = (unsigned int)(k16 * 16 * 2);
                unsigned int a[2][4], b[2][4];
#pragma unroll
                for (int mi = 0; mi < 2; mi++)
                    ldm_x4(a[mi][0], a[mi][1], a[mi][2], a[mi][3], pa + aoff[mi]*2 + kb);
#pragma unroll
                for (int g = 0; g < 2; g++)
                    ldm_x4(b[g][0], b[g][1], b[g][2], b[g][3], pb + boff[g]*2 + kb);
#pragma unroll
                for (int mi = 0; mi < 2; mi++) {
#pragma unroll
                    for (int ni = 0; ni < 4; ni++) {
                        unsigned int b0 = b[ni >> 1][(ni & 1) * 2];
                        unsigned int b1 = b[ni >> 1][(ni & 1) * 2 + 1];
                        mma_bf16(acc[mi][ni][0], acc[mi][ni][1], acc[mi][ni][2], acc[mi][ni][3],
                                 a[mi][0], a[mi][1], a[mi][2], a[mi][3], b0, b1);
                    }
                }
            }
        }
        __syncthreads();
    }

#pragma unroll
    for (int mi = 0; mi < 2; mi++) {
#pragma unroll
        for (int ni = 0; ni < 4; ni++) {
            int r0 = bm + wm + mi*16 + (lane >> 2);
            int cc = wn + ni*8 + (lane & 3)*2;
            if (outmode == 4) {
                float b0 = g_bc[bn+cc], b1 = g_bc[bn+cc+1];
                *(float2*)(Cout + (size_t)r0     * HID_ + bn + cc) =
                    make_float2(acc[mi][ni][0] + b0, acc[mi][ni][1] + b1);
                *(float2*)(Cout + (size_t)(r0+8) * HID_ + bn + cc) =
                    make_float2(acc[mi][ni][2] + b0, acc[mi][ni][3] + b1);
            } else {
                int h = bn >> 6;
                int b_0 = r0 >> 12, t_0 = r0 & (T_-1);
                int b_1 = (r0+8) >> 12, t_1 = (r0+8) & (T_-1);
                size_t i0 = ((size_t)(b_0 * H_ + h) * T_ + t_0) * D_ + cc;
                size_t i1 = ((size_t)(b_1 * H_ + h) * T_ + t_1) * D_ + cc;
                if (outmode == 1) {
                    *(float2*)(g_qk + i0) = make_float2(acc[mi][ni][0], acc[mi][ni][1]);
                    *(float2*)(g_qk + i1) = make_float2(acc[mi][ni][2], acc[mi][ni][3]);
                } else {   // outmode == 2: V -> v16 split planes directly
                    *(unsigned*)(g_v16 + i0)       = split2_u32(acc[mi][ni][0], acc[mi][ni][1], 0);
                    *(unsigned*)(g_v16 + PQ_ + i0) = split2_u32(acc[mi][ni][0], acc[mi][ni][1], 1);
                    *(unsigned*)(g_v16 + i1)       = split2_u32(acc[mi][ni][2], acc[mi][ni][3], 0);
                    *(unsigned*)(g_v16 + PQ_ + i1) = split2_u32(acc[mi][ni][2], acc[mi][ni][3], 1);
                }
            }
        }
    }
}

// ---------------- fused prep (q16/k16 split + K-norm) + LSH bucketing ----------------
// warp per (bh,t) row; lane holds elements 2*lane, 2*lane+1 of the row
__global__ __launch_bounds__(256) void prepbucket_kernel(const float* __restrict__ rot)
{
    __shared__ float srot[D_ * 32];
    int tid = threadIdx.x;
    for (int i = tid; i < D_ * 32; i += 256) srot[i] = rot[i];
    __syncthreads();

    int lane = tid & 31;
    int wid  = tid >> 5;
    int row  = blockIdx.x * 8 + wid;      // bh*T + t
    int bh   = row >> 12;
    int t    = row & (T_-1);

    size_t off = (size_t)row * D_ + lane * 2;
    float2 q = *(const float2*)(g_qk + off);

    // --- norm for K ---
    float ss = q.x*q.x + q.y*q.y;
#pragma unroll
    for (int o = 16; o > 0; o >>= 1) ss += __shfl_xor_sync(0xffffffffu, ss, o);
    float inv = 1.f / fmaxf(sqrtf(ss), 1e-12f);
    float kx = q.x * inv, ky = q.y * inv;

    // --- q16 / k16 split planes ---
    *(unsigned*)(g_q16 + off)       = split2_u32(q.x, q.y, 0);
    *(unsigned*)(g_q16 + PQ_ + off) = split2_u32(q.x, q.y, 1);
    *(unsigned*)(g_k16 + off)       = split2_u32(kx, ky, 0);
    *(unsigned*)(g_k16 + PQ_ + off) = split2_u32(kx, ky, 1);

    // --- rotation (exact same accumulation order d=0..63 as proven bucket_kernel) ---
    float r = 0.f;
#pragma unroll
    for (int d = 0; d < 64; d++) {
        float qd = (d & 1) ? __shfl_sync(0xffffffffu, q.y, d >> 1)
                           : __shfl_sync(0xffffffffu, q.x, d >> 1);
        r = fmaf(qd, srot[d * 32 + lane], r);
    }

    int i = lane & 15;
    float nr = -r;
    float v; int idx;
    if (r >= nr) { v = r;  idx = i; } else { v = nr; idx = i + 16; }
#pragma unroll
    for (int off2 = 8; off2 > 0; off2 >>= 1) {
        float ov = __shfl_down_sync(0xffffffffu, v,   off2, 16);
        int   oi = __shfl_down_sync(0xffffffffu, idx, off2, 16);
        if (ov > v || (ov == v && oi < idx)) { v = ov; idx = oi; }
    }
    if (i == 0) {
        int hash = lane >> 4;
        g_bucket[bh * TOTAL_ + hash * T_ + t] = idx + hash * NBUCK_;
    }
}

// ---------------- histogram + scan ----------------
__global__ __launch_bounds__(256) void hist_kernel()
{
    __shared__ int h[NBTOT_];
    int bh = blockIdx.x;
    int tid = threadIdx.x;
    if (tid < NBTOT_) h[tid] = 0;
    __syncthreads();
    const int* bp = g_bucket + bh * TOTAL_;
    for (int j = tid; j < TOTAL_; j += 256) atomicAdd(&h[bp[j]], 1);
    __syncthreads();
    if (tid == 0) {
        int run = 0;
        for (int b = 0; b < NBTOT_; b++) { g_bbase[bh * NBTOT_ + b] = run; run += h[b]; }
    }
}

// ---------------- stable scatter ----------------
__global__ __launch_bounds__(256) void scatter_kernel()
{
    int bh  = blockIdx.y;
    int myb = blockIdx.x;
    int tid = threadIdx.x;
    const int* bp = g_bucket + bh * TOTAL_;
    int j0 = tid * 32;
    int cnt = 0;
    for (int k = 0; k < 32; k++) cnt += (bp[j0 + k] == myb);

    __shared__ int s[256];
    s[tid] = cnt;
    __syncthreads();
    for (int off = 1; off < 256; off <<= 1) {
        int v = (tid >= off) ? s[tid - off] : 0;
        __syncthreads();
        s[tid] += v;
        __syncthreads();
    }
    int pos = g_bbase[bh * NBTOT_ + myb] + s[tid] - cnt;
    for (int k = 0; k < 32; k++) {
        int j = j0 + k;
        if (bp[j] == myb) {
            g_sidx[bh * TOTAL_ + pos] = j;
            g_undo[bh * TOTAL_ + j]   = pos;
            pos++;
        }
    }
}

// ================= FA2-style HMMA attention =================
#define LDH 72
#define SQP (128*LDH)
#define SKP (256*LDH)
#define AT2_SMEM_B ((2*SQP + 4*SKP)*2 + (128+256+128+256)*4)   // 187392

__global__ __launch_bounds__(256, 1) void attn2_kernel(const float* __restrict__ mask)
{
    extern __shared__ __nv_bfloat16 sm16[];
    __nv_bfloat16* sqh = sm16;
    int* tq = (int*)(sm16 + 2*SQP + 4*SKP);
    int* tk = tq + 128;
    int* mq = tk + 256;
    int* mk = mq + 128;

    int c   = blockIdx.x;
    int bh  = blockIdx.y;
    int tid = threadIdx.x;
    int base = bh * TOTAL_;
    const float* mrow = mask + (bh / H_) * T_;

    if (tid < 128) {
        int si = g_sidx[base + c * CL_ + tid];
        int tp = si & (T_-1);
        tq[tid] = tp;
        mq[tid] = (mrow[tp] != 0.f);
    }
    {
        int j  = tid;
        int cp = (c + NCH_ - 1) & (NCH_ - 1);
        int spos = (j < CL_) ? (c * CL_ + j) : (cp * CL_ + (j - CL_));
        int si = g_sidx[base + spos];
        int tp = si & (T_-1);
        tk[j] = tp;
        mk[j] = (mrow[tp] != 0.f);
    }
    __syncthreads();

    size_t rbo = (size_t)bh * T_;
#pragma unroll
    for (int pl = 0; pl < 2; pl++) {
        __nv_bfloat16* dq = sqh + pl*SQP;
        const __nv_bfloat16* gq = g_q16 + pl*PQ_;
        for (int i = tid; i < 128*8; i += 256) {
            int r = i >> 3, ch = i & 7;
            *(uint4*)(dq + r*LDH + ch*8) = *(const uint4*)(gq + (rbo + tq[r])*D_ + ch*8);
        }
        __nv_bfloat16* dk = sqh + 2*SQP + pl*SKP;
        __nv_bfloat16* dv = sqh + 2*SQP + 2*SKP + pl*SKP;
        const __nv_bfloat16* gk = g_k16 + pl*PQ_;
        const __nv_bfloat16* gv = g_v16 + pl*PQ_;
        for (int i = tid; i < 256*8; i += 256) {
            int r = i >> 3, ch = i & 7;
            size_t go = (rbo + tk[r])*D_ + ch*8;
            *(uint4*)(dk + r*LDH + ch*8) = *(const uint4*)(gk + go);
            *(uint4*)(dv + r*LDH + ch*8) = *(const uint4*)(gv + go);
        }
    }
    __syncthreads();

    int w = tid >> 5, lane = tid & 31;
    unsigned sb16 = smem_u32(sm16);
    unsigned kbase = sb16 + 2*SQP*2;
    unsigned vbase = sb16 + (2*SQP + 2*SKP)*2;

    unsigned qh[4][4], ql[4][4];
    {
        unsigned aQ = ((unsigned)((w*16 + (lane&7) + ((lane>>3)&1)*8) * LDH + (lane>>4)*8)) * 2;
#pragma unroll
        for (int ks = 0; ks < 4; ks++) {
            ldm_x4(qh[ks][0], qh[ks][1], qh[ks][2], qh[ks][3], sb16 + aQ + ks*32);
            ldm_x4(ql[ks][0], ql[ks][1], ql[ks][2], ql[ks][3], sb16 + SQP*2 + aQ + ks*32);
        }
    }

    int g = lane >> 2;
    int qr0 = w*16 + g, qr1 = qr0 + 8;
    int tq0 = tq[qr0], tq1 = tq[qr1];
    int mq0 = mq[qr0], mq1 = mq[qr1];

    float m0 = -INFINITY, m1 = -INFINITY, l0 = 0.f, l1 = 0.f;
    float o[8][4];
#pragma unroll
    for (int j = 0; j < 8; j++)
#pragma unroll
        for (int q = 0; q < 4; q++) o[j][q] = 0.f;

    int krl = (lane>>4)*8 + (lane&7);
    int kcl = ((lane>>3)&1)*8;
    int vrl = (lane&7) + ((lane>>3)&1)*8;
    int vcl = (lane>>4)*8;

    for (int tt = 0; tt < 4; tt++) {
        int jb = tt * 64;
        float cf[8][4];
#pragma unroll
        for (int j = 0; j < 8; j++)
#pragma unroll
            for (int q = 0; q < 4; q++) cf[j][q] = 0.f;

#pragma unroll
        for (int ks = 0; ks < 4; ks++) {
            unsigned kh[4][4], kl_[4][4];
#pragma unroll
            for (int gp = 0; gp < 4; gp++) {
                unsigned addr = kbase + ((unsigned)((jb + gp*16 + krl) * LDH + ks*16 + kcl) << 1);
                ldm_x4(kh[gp][0], kh[gp][1], kh[gp][2], kh[gp][3], addr);
                ldm_x4(kl_[gp][0], kl_[gp][1], kl_[gp][2], kl_[gp][3], addr + SKP*2);
            }
#pragma unroll
            for (int gp = 0; gp < 4; gp++) {
                mma_bf16(cf[2*gp][0], cf[2*gp][1], cf[2*gp][2], cf[2*gp][3],
                         qh[ks][0], qh[ks][1], qh[ks][2], qh[ks][3], kh[gp][0], kh[gp][1]);
                mma_bf16(cf[2*gp+1][0], cf[2*gp+1][1], cf[2*gp+1][2], cf[2*gp+1][3],
                         qh[ks][0], qh[ks][1], qh[ks][2], qh[ks][3], kh[gp][2], kh[gp][3]);
            }
#pragma unroll
            for (int gp = 0; gp < 4; gp++) {
                mma_bf16(cf[2*gp][0], cf[2*gp][1], cf[2*gp][2], cf[2*gp][3],
                         ql[ks][0], ql[ks][1], ql[ks][2], ql[ks][3], kh[gp][0], kh[gp][1]);
                mma_bf16(cf[2*gp+1][0], cf[2*gp+1][1], cf[2*gp+1][2], cf[2*gp+1][3],
                         ql[ks][0], ql[ks][1], ql[ks][2], ql[ks][3], kh[gp][2], kh[gp][3]);
            }
#pragma unroll
            for (int gp = 0; gp < 4; gp++) {
                mma_bf16(cf[2*gp][0], cf[2*gp][1], cf[2*gp][2], cf[2*gp][3],
                         qh[ks][0], qh[ks][1], qh[ks][2], qh[ks][3], kl_[gp][0], kl_[gp][1]);
                mma_bf16(cf[2*gp+1][0], cf[2*gp+1][1], cf[2*gp+1][2], cf[2*gp+1][3],
                         qh[ks][0], qh[ks][1], qh[ks][2], qh[ks][3], kl_[gp][2], kl_[gp][3]);
            }
        }

        float mx0 = -INFINITY, mx1 = -INFINITY;
#pragma unroll
        for (int j = 0; j < 8; j++) {
            int col0 = jb + j*8 + (lane&3)*2;
            int t0 = tk[col0], t1 = tk[col0+1];
            int k0 = mk[col0], k1 = mk[col0+1];
            float v00 = cf[j][0]*0.125f, v01 = cf[j][1]*0.125f;
            float v10 = cf[j][2]*0.125f, v11 = cf[j][3]*0.125f;
            if (!(mq0 && k0)) v00 = -1e9f;
            if (!(mq0 && k1)) v01 = -1e9f;
            if (!(mq1 && k0)) v10 = -1e9f;
            if (!(mq1 && k1)) v11 = -1e9f;
            if (tq0 == t0) v00 = -5e4f;
            if (tq0 == t1) v01 = -5e4f;
            if (tq1 == t0) v10 = -5e4f;
            if (tq1 == t1) v11 = -5e4f;
            cf[j][0] = v00; cf[j][1] = v01; cf[j][2] = v10; cf[j][3] = v11;
            mx0 = fmaxf(mx0, fmaxf(v00, v01));
            mx1 = fmaxf(mx1, fmaxf(v10, v11));
        }
        mx0 = fmaxf(mx0, __shfl_xor_sync(0xffffffffu, mx0, 1));
        mx0 = fmaxf(mx0, __shfl_xor_sync(0xffffffffu, mx0, 2));
        mx1 = fmaxf(mx1, __shfl_xor_sync(0xffffffffu, mx1, 1));
        mx1 = fmaxf(mx1, __shfl_xor_sync(0xffffffffu, mx1, 2));

        float nm0 = fmaxf(m0, mx0), nm1 = fmaxf(m1, mx1);
        float corr0 = __expf(m0 - nm0), corr1 = __expf(m1 - nm1);
        m0 = nm0; m1 = nm1;
        l0 *= corr0; l1 *= corr1;
#pragma unroll
        for (int j = 0; j < 8; j++) {
            o[j][0] *= corr0; o[j][1] *= corr0;
            o[j][2] *= corr1; o[j][3] *= corr1;
        }
        float s0 = 0.f, s1 = 0.f;
#pragma unroll
        for (int j = 0; j < 8; j++) {
            cf[j][0] = __expf(cf[j][0] - m0); s0 += cf[j][0];
            cf[j][1] = __expf(cf[j][1] - m0); s0 += cf[j][1];
            cf[j][2] = __expf(cf[j][2] - m1); s1 += cf[j][2];
            cf[j][3] = __expf(cf[j][3] - m1); s1 += cf[j][3];
        }
        s0 += __shfl_xor_sync(0xffffffffu, s0, 1);
        s0 += __shfl_xor_sync(0xffffffffu, s0, 2);
        s1 += __shfl_xor_sync(0xffffffffu, s1, 1);
        s1 += __shfl_xor_sync(0xffffffffu, s1, 2);
        l0 += s0; l1 += s1;

#pragma unroll
        for (int gp = 0; gp < 4; gp++) {
            unsigned aPh[4], aPl[4];
#pragma unroll
            for (int half = 0; half < 2; half++) {
                int j = 2*gp + half;
                float p0 = cf[j][0], p1 = cf[j][1], p2 = cf[j][2], p3 = cf[j][3];
                aPh[0 + 2*half] = pack_bf16(p1, p0);
                aPh[1 + 2*half] = pack_bf16(p3, p2);
                float h0 = __bfloat162float(__float2bfloat16(p0));
                float h1 = __bfloat162float(__float2bfloat16(p1));
                float h2 = __bfloat162float(__float2bfloat16(p2));
                float h3 = __bfloat162float(__float2bfloat16(p3));
                aPl[0 + 2*half] = pack_bf16(p1 - h1, p0 - h0);
                aPl[1 + 2*half] = pack_bf16(p3 - h3, p2 - h2);
            }

            unsigned vh[4][4], vl[4][4];
#pragma unroll
            for (int gd = 0; gd < 4; gd++) {
                unsigned addr = vbase + ((unsigned)((jb + gp*16 + vrl) * LDH + gd*16 + vcl) << 1);
                ldm_x4_t(vh[gd][0], vh[gd][1], vh[gd][2], vh[gd][3], addr);
                ldm_x4_t(vl[gd][0], vl[gd][1], vl[gd][2], vl[gd][3], addr + SKP*2);
            }
#pragma unroll
            for (int gd = 0; gd < 4; gd++) {
                mma_bf16(o[2*gd][0], o[2*gd][1], o[2*gd][2], o[2*gd][3],
                         aPh[0], aPh[1], aPh[2], aPh[3], vh[gd][0], vh[gd][1]);
                mma_bf16(o[2*gd+1][0], o[2*gd+1][1], o[2*gd+1][2], o[2*gd+1][3],
                         aPh[0], aPh[1], aPh[2], aPh[3], vh[gd][2], vh[gd][3]);
            }
#pragma unroll
            for (int gd = 0; gd < 4; gd++) {
                mma_bf16(o[2*gd][0], o[2*gd][1], o[2*gd][2], o[2*gd][3],
                         aPl[0], aPl[1], aPl[2], aPl[3], vh[gd][0], vh[gd][1]);
                mma_bf16(o[2*gd+1][0], o[2*gd+1][1], o[2*gd+1][2], o[2*gd+1][3],
                         aPl[0], aPl[1], aPl[2], aPl[3], vh[gd][2], vh[gd][3]);
            }
#pragma unroll
            for (int gd = 0; gd < 4; gd++) {
                mma_bf16(o[2*gd][0], o[2*gd][1], o[2*gd][2], o[2*gd][3],
                         aPh[0], aPh[1], aPh[2], aPh[3], vl[gd][0], vl[gd][1]);
                mma_bf16(o[2*gd+1][0], o[2*gd+1][1], o[2*gd+1][2], o[2*gd+1][3],
                         aPh[0], aPh[1], aPh[2], aPh[3], vl[gd][2], vl[gd][3]);
            }
        }
    }

    float inv0 = 1.f / l0, inv1 = 1.f / l1;
    int go0 = base + c * CL_ + qr0;
    int go1 = base + c * CL_ + qr1;
    if ((lane & 3) == 0) {
        g_slog[go0] = m0 + logf(l0);
        g_slog[go1] = m1 + logf(l1);
    }
#pragma unroll
    for (int j = 0; j < 8; j++) {
        int col = j*8 + (lane&3)*2;
        *(float2*)(g_so + (size_t)go0 * D_ + col) = make_float2(o[j][0]*inv0, o[j][1]*inv0);
        *(float2*)(g_so + (size_t)go1 * D_ + col) = make_float2(o[j][2]*inv1, o[j][3]*inv1);
    }
}

// ---------------- unsort + combine hash rounds (fused 2-way bf16 split) ----------------
__global__ __launch_bounds__(256) void combine_kernel()
{
    int idx  = blockIdx.x * 256 + threadIdx.x;
    int d    = idx & 63;
    int rowi = idx >> 6;
    int t    = rowi & (T_-1);
    int bh   = rowi >> 12;
    int b = bh / H_, h = bh % H_;
    int p0 = g_undo[bh * TOTAL_ + t];
    int p1 = g_undo[bh * TOTAL_ + T_ + t];
    float l0 = g_slog[bh * TOTAL_ + p0];
    float l1 = g_slog[bh * TOTAL_ + p1];
    float mm = fmaxf(l0, l1);
    float w0 = __expf(l0 - mm), w1 = __expf(l1 - mm);
    float inv = 1.f / (w0 + w1);
    float o0 = g_so[((size_t)(bh * TOTAL_ + p0)) * D_ + d];
    float o1 = g_so[((size_t)(bh * TOTAL_ + p1)) * D_ + d];
    float val = (w0 * o0 + w1 * o1) * inv;
    size_t oidx = ((size_t)(b * T_ + t)) * HID_ + h * D_ + d;
    __nv_bfloat16 hi = __float2bfloat16(val);
    g_as[oidx] = hi;
    g_as[(size_t)M_ * HID_ + oidx] = __float2bfloat16(val - __bfloat162float(hi));
}

// ---------------- launcher ----------------
extern "C" void kernel_launch(void* const* d_in, const int* in_sizes, int n_in,
                              void* d_out, int out_size)
{
    const float* X    = (const float*)d_in[0];
    const float* mask = (const float*)d_in[1];
    const float* W_qk = (const float*)d_in[2];
    const float* W_v  = (const float*)d_in[3];
    const float* rot  = (const float*)d_in[4];
    const float* W_to = (const float*)d_in[5];
    const float* b_to = (const float*)d_in[6];
    const float* W_o  = (const float*)d_in[7];
    const float* b_o  = (const float*)d_in[8];
    float* out = (float*)d_out;

    cudaFuncSetAttribute(mma_gemm_kernel, cudaFuncAttributeMaxDynamicSharedMemorySize, GEMM_SMEM_MAX);
    cudaFuncSetAttribute(attn2_kernel,    cudaFuncAttributeMaxDynamicSharedMemorySize, AT2_SMEM_B);

    const int NX4 = M_ * HID_ / 4;
    const int NW4 = HID_ * HID_ / 4;
    const int GX  = (NX4 + 255) / 256;
    const int GW  = (NW4 + 255) / 256;
    dim3 gg(HID_ / 64, M_ / 128);   // (12, 128)

    // QK projection: 3-way split (exact buckets); V: 2-way -> v16 planes directly
    split_kernel<<<GX, 256>>>(X,    NX4, 3, 0, 0);
    split_kernel<<<GW, 256>>>(W_qk, NW4, 3, 1, 0);
    mma_gemm_kernel<<<gg, 256, 2*STAGE3_B>>>(nullptr, 1, 3);   // -> g_qk
    split_kernel<<<GW, 256>>>(W_v,  NW4, 2, 1, 0);
    mma_gemm_kernel<<<gg, 256, 2*STAGE2_B>>>(nullptr, 2, 2);   // -> g_v16 planes

    prepbucket_kernel<<<(BH_ * T_) / 8, 256>>>(rot);           // q16/k16 + buckets (one g_qk read)
    hist_kernel<<<BH_, 256>>>();
    scatter_kernel<<<dim3(NBTOT_, BH_), 256>>>();

    attn2_kernel<<<dim3(NCH_, BH_), 256, AT2_SMEM_B>>>(mask);

    combine_kernel<<<(BH_ * T_ * D_) / 256, 256>>>();          // -> g_as planes (fused split)

    // combined output weight: W_c = W_o @ W_to, b_c = b_o + W_o @ b_to
    transpose768_kernel<<<(HID_*HID_ + 255)/256, 256>>>(W_to);
    sgemm768_kernel<<<dim3(HID_/64, HID_/128), 256>>>(W_o);
    biascomb_kernel<<<(HID_ + 255)/256, 256>>>(b_to, b_o, W_o);
    split_kernel<<<GW, 256>>>(nullptr, NW4, 2, 1, 3);          // g_wc -> g_bs

    mma_gemm_kernel<<<gg, 256, 2*STAGE2_B>>>(out, 4, 2);       // -> d_out
}

// round 16
// speedup vs baseline: 1.7098x; 1.0073x over previous
#include <cuda_runtime.h>
#include <cuda_bf16.h>
#include <cstdint>
#include <math.h>

#define B_      4
#define T_      4096
#define HID_    768
#define H_      12
#define D_      64
#define BH_     48
#define NBUCK_  32
#define NBTOT_  64
#define TOTAL_  8192
#define NCH_    64
#define CL_     128
#define M_      (B_*T_)      // 16384

// ---------------- scratch (static device globals; no allocation) ----------------
__device__ float g_qk[BH_*T_*D_];            // [bh][t][d]
__device__ int   g_bucket[BH_*TOTAL_];
__device__ int   g_sidx[BH_*TOTAL_];
__device__ int   g_undo[BH_*TOTAL_];
__device__ int   g_bbase[BH_*NBTOT_];
__device__ float g_so  [BH_*TOTAL_*D_];
__device__ float g_slog[BH_*TOTAL_];
// combined output weight path
__device__ float g_wc [HID_*HID_];           // W_o @ W_to
__device__ float g_bc [HID_];                // b_o + W_o @ b_to
// bf16 split planes for GEMMs
__device__ __nv_bfloat16 g_as[3 * M_ * HID_];
__device__ __nv_bfloat16 g_bs[3 * HID_ * HID_];
// bf16 2-split planes for attention: [2][bh][t][64]
#define PQ_ ((size_t)BH_*T_*D_)
__device__ __nv_bfloat16 g_q16[2*BH_*T_*D_];
__device__ __nv_bfloat16 g_k16[2*BH_*T_*D_];   // normalized K
__device__ __nv_bfloat16 g_v16[2*BH_*T_*D_];

__device__ __forceinline__ unsigned int smem_u32(const void* p) {
    unsigned int a;
    asm("{ .reg .u64 t; cvta.to.shared.u64 t, %1; cvt.u32.u64 %0, t; }" : "=r"(a) : "l"(p));
    return a;
}
__device__ __forceinline__ void ldm_x4(unsigned int& r0, unsigned int& r1,
                                       unsigned int& r2, unsigned int& r3,
                                       unsigned int addr) {
    asm volatile("ldmatrix.sync.aligned.m8n8.x4.shared.b16 {%0,%1,%2,%3}, [%4];"
                 : "=r"(r0), "=r"(r1), "=r"(r2), "=r"(r3) : "r"(addr));
}
__device__ __forceinline__ void ldm_x4_t(unsigned int& r0, unsigned int& r1,
                                         unsigned int& r2, unsigned int& r3,
                                         unsigned int addr) {
    asm volatile("ldmatrix.sync.aligned.m8n8.x4.trans.shared.b16 {%0,%1,%2,%3}, [%4];"
                 : "=r"(r0), "=r"(r1), "=r"(r2), "=r"(r3) : "r"(addr));
}
__device__ __forceinline__ void mma_bf16(float& c0, float& c1, float& c2, float& c3,
                                         unsigned int a0, unsigned int a1,
                                         unsigned int a2, unsigned int a3,
                                         unsigned int b0, unsigned int b1) {
    asm volatile("mma.sync.aligned.m16n8k16.row.col.f32.bf16.bf16.f32 "
                 "{%0,%1,%2,%3}, {%4,%5,%6,%7}, {%8,%9}, {%0,%1,%2,%3};"
                 : "+f"(c0), "+f"(c1), "+f"(c2), "+f"(c3)
                 : "r"(a0), "r"(a1), "r"(a2), "r"(a3), "r"(b0), "r"(b1));
}
__device__ __forceinline__ unsigned int pack_bf16(float hi, float lo) {
    unsigned int r;
    asm("cvt.rn.bf16x2.f32 %0, %1, %2;" : "=r"(r) : "f"(hi), "f"(lo));
    return r;
}
__device__ __forceinline__ void cp8(unsigned int dst, const void* src) {
    asm volatile("cp.async.ca.shared.global [%0], [%1], 8;" :: "r"(dst), "l"(src));
}
__device__ __forceinline__ void cp_commit() {
    asm volatile("cp.async.commit_group;" ::: "memory");
}
__device__ __forceinline__ unsigned int split2_u32(float a, float b, int pl) {
    __nv_bfloat16 ha = __float2bfloat16(a), hb = __float2bfloat16(b);
    if (pl == 0)
        return (unsigned int)__bfloat16_as_ushort(ha) | ((unsigned int)__bfloat16_as_ushort(hb) << 16);
    __nv_bfloat16 la = __float2bfloat16(a - __bfloat162float(ha));
    __nv_bfloat16 lb = __float2bfloat16(b - __bfloat162float(hb));
    return (unsigned int)__bfloat16_as_ushort(la) | ((unsigned int)__bfloat16_as_ushort(lb) << 16);
}

// ---------------- fp32 -> ns bf16 split planes (for GEMMs) ----------------
// which: 0 -> g_as, 1 -> g_bs     insel: 0 -> src param, 3 -> g_wc
__global__ __launch_bounds__(256) void split_kernel(const float* __restrict__ srcp,
                                                    int n4, int ns, int which, int insel)
{
    int idx = blockIdx.x * 256 + threadIdx.x;
    if (idx >= n4) return;
    const float* src = (insel == 0) ? srcp : (const float*)g_wc;
    float4 v = ((const float4*)src)[idx];
    __nv_bfloat16* dst = which ? g_bs : g_as;
    size_t stride = which ? (size_t)HID_ * HID_ : (size_t)M_ * HID_;
    float rx = v.x, ry = v.y, rz = v.z, rw = v.w;
    for (int s = 0; s < ns; s++) {
        __nv_bfloat16 bx = __float2bfloat16(rx), by = __float2bfloat16(ry);
        __nv_bfloat16 bz = __float2bfloat16(rz), bw = __float2bfloat16(rw);
        rx -= __bfloat162float(bx); ry -= __bfloat162float(by);
        rz -= __bfloat162float(bz); rw -= __bfloat162float(bw);
        uint2 u;
        u.x = (unsigned int)__bfloat16_as_ushort(bx) | ((unsigned int)__bfloat16_as_ushort(by) << 16);
        u.y = (unsigned int)__bfloat16_as_ushort(bz) | ((unsigned int)__bfloat16_as_ushort(bw) << 16);
        *(uint2*)(dst + s * stride + (size_t)idx * 4) = u;
    }
}

// ---------------- fp32 SGEMM 768x768x768: g_wc = W_o @ W_to (W_to loaded transposed) ----
__global__ __launch_bounds__(256) void sgemm768_kernel(const float* __restrict__ A,
                                                       const float* __restrict__ Wto)
{
    __shared__ float As[16][128];
    __shared__ float Ws[16][64];
    const int K = HID_;
    int bm = blockIdx.y * 128;
    int bn = blockIdx.x * 64;
    int tid = threadIdx.x;
    int tx = tid & 15, ty = tid >> 4;

    float acc[8][4];
#pragma unroll
    for (int i = 0; i < 8; i++)
#pragma unroll
        for (int j = 0; j < 4; j++) acc[i][j] = 0.f;

    for (int k0 = 0; k0 < K; k0 += 16) {
#pragma unroll
        for (int li = 0; li < 2; li++) {
            int i   = tid + li * 256;
            int row = i >> 2;
            int kq  = (i & 3) << 2;
            float4 av = *(const float4*)(A + (size_t)(bm + row) * K + k0 + kq);
            As[kq+0][row] = av.x; As[kq+1][row] = av.y;
            As[kq+2][row] = av.z; As[kq+3][row] = av.w;
        }
        {
            int row = tid >> 2;           // column of W_to
            int kq  = (tid & 3) << 2;     // k within chunk
#pragma unroll
            for (int i = 0; i < 4; i++)
                Ws[kq+i][row] = Wto[(size_t)(k0 + kq + i) * K + bn + row];
        }
        __syncthreads();
#pragma unroll
        for (int kk = 0; kk < 16; kk++) {
            float4 a0 = *(const float4*)&As[kk][ty*8];
            float4 a1 = *(const float4*)&As[kk][ty*8 + 4];
            float4 bv = *(const float4*)&Ws[kk][tx*4];
            float a[8] = {a0.x,a0.y,a0.z,a0.w,a1.x,a1.y,a1.z,a1.w};
            float b[4] = {bv.x,bv.y,bv.z,bv.w};
#pragma unroll
            for (int i = 0; i < 8; i++)
#pragma unroll
                for (int j = 0; j < 4; j++)
                    acc[i][j] = fmaf(a[i], b[j], acc[i][j]);
        }
        __syncthreads();
    }

    int col = bn + tx * 4;
#pragma unroll
    for (int i = 0; i < 8; i++) {
        int row = bm + ty * 8 + i;
        *(float4*)(g_wc + (size_t)row * HID_ + col) =
            make_float4(acc[i][0], acc[i][1], acc[i][2], acc[i][3]);
    }
}

// ---------------- combined bias: g_bc = b_o + W_o @ b_to ----------------
__global__ __launch_bounds__(256) void biascomb_kernel(const float* __restrict__ b_to,
                                                       const float* __restrict__ b_o,
                                                       const float* __restrict__ W_o)
{
    int i = blockIdx.x * 256 + threadIdx.x;
    if (i >= HID_) return;
    float s = b_o[i];
    for (int k = 0; k < HID_; k++) s = fmaf(W_o[(size_t)i * HID_ + k], b_to[k], s);
    g_bc[i] = s;
}

// ================= split-bf16 GEMM (M128 N64 K32, 2-stage cp.async) ======
#define LDA_ 40
#define A_SP_H (128*LDA_)
#define B_SP_H (64*LDA_)
#define STAGE3_B ((3*A_SP_H + 3*B_SP_H)*2)   // 46080
#define STAGE2_B ((2*A_SP_H + 2*B_SP_H)*2)   // 30720
#define GEMM_SMEM_MAX (2*STAGE3_B)           // 92160

// outmode: 1=g_qk merged-head, 2=g_v16 split planes merged-head, 4=Cout + g_bc bias
// ns==3 path (QK): EXACT R13 pass-order -> bit-identical buckets. ns==2: frag-reuse order.
__global__ __launch_bounds__(256) void mma_gemm_kernel(
    float* __restrict__ Cout, int outmode, int ns)
{
    extern __shared__ char smem[];
    unsigned int sbase = smem_u32(smem);

    int tid = threadIdx.x, wid = tid >> 5, lane = tid & 31;
    int bm = blockIdx.y * 128, bn = blockIdx.x * 64;
    int wm = (wid & 3) * 32;
    int wn = (wid >> 2) * 32;

    const unsigned int stage_b = (ns == 2) ? STAGE2_B : STAGE3_B;
    const unsigned int b_off   = (unsigned int)(ns * A_SP_H * 2);

    float acc[2][4][4];
#pragma unroll
    for (int mi = 0; mi < 2; mi++)
#pragma unroll
        for (int ni = 0; ni < 4; ni++)
#pragma unroll
            for (int q = 0; q < 4; q++) acc[mi][ni][q] = 0.f;

    int arow = tid >> 3, aqc = tid & 7;
    int ra  = (lane & 7) + ((lane >> 3) & 1) * 8;
    int aco = (lane >> 4) * 8;
    unsigned int aoff[2];
#pragma unroll
    for (int mi = 0; mi < 2; mi++)
        aoff[mi] = (unsigned int)((wm + mi*16 + ra) * LDA_ + aco);
    int rb  = lane & 7;
    int bco = ((lane >> 3) & 1) * 8;
    unsigned int boff[2];
#pragma unroll
    for (int g = 0; g < 2; g++)
        boff[g] = (unsigned int)((wn + (g*2 + (lane >> 4))*8 + rb) * LDA_ + bco);

    const size_t ASZ = (size_t)M_ * HID_;
    const size_t BSZ = (size_t)HID_ * HID_;

    auto issue = [&](int kc, int buf) {
        int k0 = kc * 32;
        unsigned int sbuf = sbase + buf * stage_b;
        for (int s = 0; s < ns; s++) {
            const __nv_bfloat16* ga = g_as + s * ASZ + (size_t)(bm + arow) * HID_ + k0 + aqc * 4;
            unsigned int da = sbuf + (unsigned int)((s * A_SP_H + arow * LDA_ + aqc * 4) * 2);
#pragma unroll
            for (int i = 0; i < 4; i++)
                cp8(da + (unsigned int)(i * 32 * LDA_ * 2), ga + (size_t)i * 32 * HID_);
            const __nv_bfloat16* gb = g_bs + s * BSZ + (size_t)(bn + arow) * HID_ + k0 + aqc * 4;
            unsigned int db = sbuf + b_off + (unsigned int)((s * B_SP_H + arow * LDA_ + aqc * 4) * 2);
#pragma unroll
            for (int i = 0; i < 2; i++)
                cp8(db + (unsigned int)(i * 32 * LDA_ * 2), gb + (size_t)i * 32 * HID_);
        }
        cp_commit();
    };

    issue(0, 0);

    for (int kc = 0; kc < 24; kc++) {
        if (kc < 23) {
            issue(kc + 1, (kc + 1) & 1);
            asm volatile("cp.async.wait_group 1;" ::: "memory");
        } else {
            asm volatile("cp.async.wait_group 0;" ::: "memory");
        }
        __syncthreads();

        unsigned int sbuf = sbase + (kc & 1) * stage_b;
        if (ns == 3) {
            // ===== EXACT R13 path (bit-identical qk) =====
            const int PA[6] = {0, 0, 1, 1, 0, 2};
            const int PB[6] = {0, 1, 0, 1, 2, 0};
            for (int p = 0; p < 6; p++) {
                unsigned int pa = sbuf + (unsigned int)(PA[p] * A_SP_H * 2);
                unsigned int pb = sbuf + b_off + (unsigned int)(PB[p] * B_SP_H * 2);
#pragma unroll
                for (int k16 = 0; k16 < 2; k16++) {
                    unsigned int kb = (unsigned int)(k16 * 16 * 2);
                    unsigned int a[2][4], b[2][4];
#pragma unroll
                    for (int mi = 0; mi < 2; mi++)
                        ldm_x4(a[mi][0], a[mi][1], a[mi][2], a[mi][3], pa + aoff[mi]*2 + kb);
#pragma unroll
                    for (int g = 0; g < 2; g++)
                        ldm_x4(b[g][0], b[g][1], b[g][2], b[g][3], pb + boff[g]*2 + kb);
#pragma unroll
                    for (int mi = 0; mi < 2; mi++) {
#pragma unroll
                        for (int ni = 0; ni < 4; ni++) {
                            unsigned int b0 = b[ni >> 1][(ni & 1) * 2];
                            unsigned int b1 = b[ni >> 1][(ni & 1) * 2 + 1];
                            mma_bf16(acc[mi][ni][0], acc[mi][ni][1], acc[mi][ni][2], acc[mi][ni][3],
                                     a[mi][0], a[mi][1], a[mi][2], a[mi][3], b0, b1);
                        }
                    }
                }
            }
        } else {
            // ===== ns==2 frag-reuse path (smooth outputs; reorder OK) =====
            // passes: (a0,b0), (a0,b1), (a1,b0)
#pragma unroll
            for (int k16 = 0; k16 < 2; k16++) {
                unsigned int kb = (unsigned int)(k16 * 16 * 2);
                unsigned int af[2][2][4], bf[2][2][4];
#pragma unroll
                for (int s = 0; s < 2; s++) {
                    unsigned int pa = sbuf + (unsigned int)(s * A_SP_H * 2);
                    unsigned int pb = sbuf + b_off + (unsigned int)(s * B_SP_H * 2);
#pragma unroll
                    for (int mi = 0; mi < 2; mi++)
                        ldm_x4(af[s][mi][0], af[s][mi][1], af[s][mi][2], af[s][mi][3],
                               pa + aoff[mi]*2 + kb);
#pragma unroll
                    for (int g = 0; g < 2; g++)
                        ldm_x4(bf[s][g][0], bf[s][g][1], bf[s][g][2], bf[s][g][3],
                               pb + boff[g]*2 + kb);
                }
                const int QA[3] = {0, 0, 1};
                const int QB[3] = {0, 1, 0};
#pragma unroll
                for (int p = 0; p < 3; p++) {
#pragma unroll
                    for (int mi = 0; mi < 2; mi++) {
#pragma unroll
                        for (int ni = 0; ni < 4; ni++) {
                            unsigned int b0 = bf[QB[p]][ni >> 1][(ni & 1) * 2];
                            unsigned int b1 = bf[QB[p]][ni >> 1][(ni & 1) * 2 + 1];
                            mma_bf16(acc[mi][ni][0], acc[mi][ni][1], acc[mi][ni][2], acc[mi][ni][3],
                                     af[QA[p]][mi][0], af[QA[p]][mi][1],
                                     af[QA[p]][mi][2], af[QA[p]][mi][3], b0, b1);
                        }
                    }
                }
            }
        }
        __syncthreads();
    }

#pragma unroll
    for (int mi = 0; mi < 2; mi++) {
#pragma unroll
        for (int ni = 0; ni < 4; ni++) {
            int r0 = bm + wm + mi*16 + (lane >> 2);
            int cc = wn + ni*8 + (lane & 3)*2;
            if (outmode == 4) {
                float b0 = g_bc[bn+cc], b1 = g_bc[bn+cc+1];
                *(float2*)(Cout + (size_t)r0     * HID_ + bn + cc) =
                    make_float2(acc[mi][ni][0] + b0, acc[mi][ni][1] + b1);
                *(float2*)(Cout + (size_t)(r0+8) * HID_ + bn + cc) =
                    make_float2(acc[mi][ni][2] + b0, acc[mi][ni][3] + b1);
            } else {
                int h = bn >> 6;
                int b_0 = r0 >> 12, t_0 = r0 & (T_-1);
                int b_1 = (r0+8) >> 12, t_1 = (r0+8) & (T_-1);
                size_t i0 = ((size_t)(b_0 * H_ + h) * T_ + t_0) * D_ + cc;
                size_t i1 = ((size_t)(b_1 * H_ + h) * T_ + t_1) * D_ + cc;
                if (outmode == 1) {
                    *(float2*)(g_qk + i0) = make_float2(acc[mi][ni][0], acc[mi][ni][1]);
                    *(float2*)(g_qk + i1) = make_float2(acc[mi][ni][2], acc[mi][ni][3]);
                } else {
                    *(unsigned*)(g_v16 + i0)       = split2_u32(acc[mi][ni][0], acc[mi][ni][1], 0);
                    *(unsigned*)(g_v16 + PQ_ + i0) = split2_u32(acc[mi][ni][0], acc[mi][ni][1], 1);
                    *(unsigned*)(g_v16 + i1)       = split2_u32(acc[mi][ni][2], acc[mi][ni][3], 0);
                    *(unsigned*)(g_v16 + PQ_ + i1) = split2_u32(acc[mi][ni][2], acc[mi][ni][3], 1);
                }
            }
        }
    }
}

// ---------------- fused prep (q16/k16 split + K-norm) + LSH bucketing ----------------
__global__ __launch_bounds__(256) void prepbucket_kernel(const float* __restrict__ rot)
{
    __shared__ float srot[D_ * 32];
    int tid = threadIdx.x;
    for (int i = tid; i < D_ * 32; i += 256) srot[i] = rot[i];
    __syncthreads();

    int lane = tid & 31;
    int wid  = tid >> 5;
    int row  = blockIdx.x * 8 + wid;      // bh*T + t
    int bh   = row >> 12;
    int t    = row & (T_-1);

    size_t off = (size_t)row * D_ + lane * 2;
    float2 q = *(const float2*)(g_qk + off);

    float ss = q.x*q.x + q.y*q.y;
#pragma unroll
    for (int o = 16; o > 0; o >>= 1) ss += __shfl_xor_sync(0xffffffffu, ss, o);
    float inv = 1.f / fmaxf(sqrtf(ss), 1e-12f);
    float kx = q.x * inv, ky = q.y * inv;

    *(unsigned*)(g_q16 + off)       = split2_u32(q.x, q.y, 0);
    *(unsigned*)(g_q16 + PQ_ + off) = split2_u32(q.x, q.y, 1);
    *(unsigned*)(g_k16 + off)       = split2_u32(kx, ky, 0);
    *(unsigned*)(g_k16 + PQ_ + off) = split2_u32(kx, ky, 1);

    float r = 0.f;
#pragma unroll
    for (int d = 0; d < 64; d++) {
        float qd = (d & 1) ? __shfl_sync(0xffffffffu, q.y, d >> 1)
                           : __shfl_sync(0xffffffffu, q.x, d >> 1);
        r = fmaf(qd, srot[d * 32 + lane], r);
    }

    int i = lane & 15;
    float nr = -r;
    float v; int idx;
    if (r >= nr) { v = r;  idx = i; } else { v = nr; idx = i + 16; }
#pragma unroll
    for (int off2 = 8; off2 > 0; off2 >>= 1) {
        float ov = __shfl_down_sync(0xffffffffu, v,   off2, 16);
        int   oi = __shfl_down_sync(0xffffffffu, idx, off2, 16);
        if (ov > v || (ov == v && oi < idx)) { v = ov; idx = oi; }
    }
    if (i == 0) {
        int hash = lane >> 4;
        g_bucket[bh * TOTAL_ + hash * T_ + t] = idx + hash * NBUCK_;
    }
}

// ---------------- histogram + scan ----------------
__global__ __launch_bounds__(256) void hist_kernel()
{
    __shared__ int h[NBTOT_];
    int bh = blockIdx.x;
    int tid = threadIdx.x;
    if (tid < NBTOT_) h[tid] = 0;
    __syncthreads();
    const int* bp = g_bucket + bh * TOTAL_;
    for (int j = tid; j < TOTAL_; j += 256) atomicAdd(&h[bp[j]], 1);
    __syncthreads();
    if (tid == 0) {
        int run = 0;
        for (int b = 0; b < NBTOT_; b++) { g_bbase[bh * NBTOT_ + b] = run; run += h[b]; }
    }
}

// ---------------- stable scatter ----------------
__global__ __launch_bounds__(256) void scatter_kernel()
{
    int bh  = blockIdx.y;
    int myb = blockIdx.x;
    int tid = threadIdx.x;
    const int* bp = g_bucket + bh * TOTAL_;
    int j0 = tid * 32;
    int cnt = 0;
    for (int k = 0; k < 32; k++) cnt += (bp[j0 + k] == myb);

    __shared__ int s[256];
    s[tid] = cnt;
    __syncthreads();
    for (int off = 1; off < 256; off <<= 1) {
        int v = (tid >= off) ? s[tid - off] : 0;
        __syncthreads();
        s[tid] += v;
        __syncthreads();
    }
    int pos = g_bbase[bh * NBTOT_ + myb] + s[tid] - cnt;
    for (int k = 0; k < 32; k++) {
        int j = j0 + k;
        if (bp[j] == myb) {
            g_sidx[bh * TOTAL_ + pos] = j;
            g_undo[bh * TOTAL_ + j]   = pos;
            pos++;
        }
    }
}

// ================= FA2-style HMMA attention =================
#define LDH 72
#define SQP (128*LDH)
#define SKP (256*LDH)
#define AT2_SMEM_B ((2*SQP + 4*SKP)*2 + (128+256+128+256)*4)   // 187392

__global__ __launch_bounds__(256, 1) void attn2_kernel(const float* __restrict__ mask)
{
    extern __shared__ __nv_bfloat16 sm16[];
    __nv_bfloat16* sqh = sm16;
    int* tq = (int*)(sm16 + 2*SQP + 4*SKP);
    int* tk = tq + 128;
    int* mq = tk + 256;
    int* mk = mq + 128;

    int c   = blockIdx.x;
    int bh  = blockIdx.y;
    int tid = threadIdx.x;
    int base = bh * TOTAL_;
    const float* mrow = mask + (bh / H_) * T_;

    if (tid < 128) {
        int si = g_sidx[base + c * CL_ + tid];
        int tp = si & (T_-1);
        tq[tid] = tp;
        mq[tid] = (mrow[tp] != 0.f);
    }
    {
        int j  = tid;
        int cp = (c + NCH_ - 1) & (NCH_ - 1);
        int spos = (j < CL_) ? (c * CL_ + j) : (cp * CL_ + (j - CL_));
        int si = g_sidx[base + spos];
        int tp = si & (T_-1);
        tk[j] = tp;
        mk[j] = (mrow[tp] != 0.f);
    }
    __syncthreads();

    size_t rbo = (size_t)bh * T_;
#pragma unroll
    for (int pl = 0; pl < 2; pl++) {
        __nv_bfloat16* dq = sqh + pl*SQP;
        const __nv_bfloat16* gq = g_q16 + pl*PQ_;
        for (int i = tid; i < 128*8; i += 256) {
            int r = i >> 3, ch = i & 7;
            *(uint4*)(dq + r*LDH + ch*8) = *(const uint4*)(gq + (rbo + tq[r])*D_ + ch*8);
        }
        __nv_bfloat16* dk = sqh + 2*SQP + pl*SKP;
        __nv_bfloat16* dv = sqh + 2*SQP + 2*SKP + pl*SKP;
        const __nv_bfloat16* gk = g_k16 + pl*PQ_;
        const __nv_bfloat16* gv = g_v16 + pl*PQ_;
        for (int i = tid; i < 256*8; i += 256) {
            int r = i >> 3, ch = i & 7;
            size_t go = (rbo + tk[r])*D_ + ch*8;
            *(uint4*)(dk + r*LDH + ch*8) = *(const uint4*)(gk + go);
            *(uint4*)(dv + r*LDH + ch*8) = *(const uint4*)(gv + go);
        }
    }
    __syncthreads();

    int w = tid >> 5, lane = tid & 31;
    unsigned sb16 = smem_u32(sm16);
    unsigned kbase = sb16 + 2*SQP*2;
    unsigned vbase = sb16 + (2*SQP + 2*SKP)*2;

    unsigned qh[4][4], ql[4][4];
    {
        unsigned aQ = ((unsigned)((w*16 + (lane&7) + ((lane>>3)&1)*8) * LDH + (lane>>4)*8)) * 2;
#pragma unroll
        for (int ks = 0; ks < 4; ks++) {
            ldm_x4(qh[ks][0], qh[ks][1], qh[ks][2], qh[ks][3], sb16 + aQ + ks*32);
            ldm_x4(ql[ks][0], ql[ks][1], ql[ks][2], ql[ks][3], sb16 + SQP*2 + aQ + ks*32);
        }
    }

    int g = lane >> 2;
    int qr0 = w*16 + g, qr1 = qr0 + 8;
    int tq0 = tq[qr0], tq1 = tq[qr1];
    int mq0 = mq[qr0], mq1 = mq[qr1];

    float m0 = -INFINITY, m1 = -INFINITY, l0 = 0.f, l1 = 0.f;
    float o[8][4];
#pragma unroll
    for (int j = 0; j < 8; j++)
#pragma unroll
        for (int q = 0; q < 4; q++) o[j][q] = 0.f;

    int krl = (lane>>4)*8 + (lane&7);
    int kcl = ((lane>>3)&1)*8;
    int vrl = (lane&7) + ((lane>>3)&1)*8;
    int vcl = (lane>>4)*8;

    for (int tt = 0; tt < 4; tt++) {
        int jb = tt * 64;
        float cf[8][4];
#pragma unroll
        for (int j = 0; j < 8; j++)
#pragma unroll
            for (int q = 0; q < 4; q++) cf[j][q] = 0.f;

#pragma unroll
        for (int ks = 0; ks < 4; ks++) {
            unsigned kh[4][4], kl_[4][4];
#pragma unroll
            for (int gp = 0; gp < 4; gp++) {
                unsigned addr = kbase + ((unsigned)((jb + gp*16 + krl) * LDH + ks*16 + kcl) << 1);
                ldm_x4(kh[gp][0], kh[gp][1], kh[gp][2], kh[gp][3], addr);
                ldm_x4(kl_[gp][0], kl_[gp][1], kl_[gp][2], kl_[gp][3], addr + SKP*2);
            }
#pragma unroll
            for (int gp = 0; gp < 4; gp++) {
                mma_bf16(cf[2*gp][0], cf[2*gp][1], cf[2*gp][2], cf[2*gp][3],
                         qh[ks][0], qh[ks][1], qh[ks][2], qh[ks][3], kh[gp][0], kh[gp][1]);
                mma_bf16(cf[2*gp+1][0], cf[2*gp+1][1], cf[2*gp+1][2], cf[2*gp+1][3],
                         qh[ks][0], qh[ks][1], qh[ks][2], qh[ks][3], kh[gp][2], kh[gp][3]);
            }
#pragma unroll
            for (int gp = 0; gp < 4; gp++) {
                mma_bf16(cf[2*gp][0], cf[2*gp][1], cf[2*gp][2], cf[2*gp][3],
                         ql[ks][0], ql[ks][1], ql[ks][2], ql[ks][3], kh[gp][0], kh[gp][1]);
                mma_bf16(cf[2*gp+1][0], cf[2*gp+1][1], cf[2*gp+1][2], cf[2*gp+1][3],
                         ql[ks][0], ql[ks][1], ql[ks][2], ql[ks][3], kh[gp][2], kh[gp][3]);
            }
#pragma unroll
            for (int gp = 0; gp < 4; gp++) {
                mma_bf16(cf[2*gp][0], cf[2*gp][1], cf[2*gp][2], cf[2*gp][3],
                         qh[ks][0], qh[ks][1], qh[ks][2], qh[ks][3], kl_[gp][0], kl_[gp][1]);
                mma_bf16(cf[2*gp+1][0], cf[2*gp+1][1], cf[2*gp+1][2], cf[2*gp+1][3],
                         qh[ks][0], qh[ks][1], qh[ks][2], qh[ks][3], kl_[gp][2], kl_[gp][3]);
            }
        }

        float mx0 = -INFINITY, mx1 = -INFINITY;
#pragma unroll
        for (int j = 0; j < 8; j++) {
            int col0 = jb + j*8 + (lane&3)*2;
            int t0 = tk[col0], t1 = tk[col0+1];
            int k0 = mk[col0], k1 = mk[col0+1];
            float v00 = cf[j][0]*0.125f, v01 = cf[j][1]*0.125f;
            float v10 = cf[j][2]*0.125f, v11 = cf[j][3]*0.125f;
            if (!(mq0 && k0)) v00 = -1e9f;
            if (!(mq0 && k1)) v01 = -1e9f;
            if (!(mq1 && k0)) v10 = -1e9f;
            if (!(mq1 && k1)) v11 = -1e9f;
            if (tq0 == t0) v00 = -5e4f;
            if (tq0 == t1) v01 = -5e4f;
            if (tq1 == t0) v10 = -5e4f;
            if (tq1 == t1) v11 = -5e4f;
            cf[j][0] = v00; cf[j][1] = v01; cf[j][2] = v10; cf[j][3] = v11;
            mx0 = fmaxf(mx0, fmaxf(v00, v01));
            mx1 = fmaxf(mx1, fmaxf(v10, v11));
        }
        mx0 = fmaxf(mx0, __shfl_xor_sync(0xffffffffu, mx0, 1));
        mx0 = fmaxf(mx0, __shfl_xor_sync(0xffffffffu, mx0, 2));
        mx1 = fmaxf(mx1, __shfl_xor_sync(0xffffffffu, mx1, 1));
        mx1 = fmaxf(mx1, __shfl_xor_sync(0xffffffffu, mx1, 2));

        float nm0 = fmaxf(m0, mx0), nm1 = fmaxf(m1, mx1);
        float corr0 = __expf(m0 - nm0), corr1 = __expf(m1 - nm1);
        m0 = nm0; m1 = nm1;
        l0 *= corr0; l1 *= corr1;
#pragma unroll
        for (int j = 0; j < 8; j++) {
            o[j][0] *= corr0; o[j][1] *= corr0;
            o[j][2] *= corr1; o[j][3] *= corr1;
        }
        float s0 = 0.f, s1 = 0.f;
#pragma unroll
        for (int j = 0; j < 8; j++) {
            cf[j][0] = __expf(cf[j][0] - m0); s0 += cf[j][0];
            cf[j][1] = __expf(cf[j][1] - m0); s0 += cf[j][1];
            cf[j][2] = __expf(cf[j][2] - m1); s1 += cf[j][2];
            cf[j][3] = __expf(cf[j][3] - m1); s1 += cf[j][3];
        }
        s0 += __shfl_xor_sync(0xffffffffu, s0, 1);
        s0 += __shfl_xor_sync(0xffffffffu, s0, 2);
        s1 += __shfl_xor_sync(0xffffffffu, s1, 1);
        s1 += __shfl_xor_sync(0xffffffffu, s1, 2);
        l0 += s0; l1 += s1;

#pragma unroll
        for (int gp = 0; gp < 4; gp++) {
            unsigned aPh[4], aPl[4];
#pragma unroll
            for (int half = 0; half < 2; half++) {
                int j = 2*gp + half;
                float p0 = cf[j][0], p1 = cf[j][1], p2 = cf[j][2], p3 = cf[j][3];
                aPh[0 + 2*half] = pack_bf16(p1, p0);
                aPh[1 + 2*half] = pack_bf16(p3, p2);
                float h0 = __bfloat162float(__float2bfloat16(p0));
                float h1 = __bfloat162float(__float2bfloat16(p1));
                float h2 = __bfloat162float(__float2bfloat16(p2));
                float h3 = __bfloat162float(__float2bfloat16(p3));
                aPl[0 + 2*half] = pack_bf16(p1 - h1, p0 - h0);
                aPl[1 + 2*half] = pack_bf16(p3 - h3, p2 - h2);
            }

            unsigned vh[4][4], vl[4][4];
#pragma unroll
            for (int gd = 0; gd < 4; gd++) {
                unsigned addr = vbase + ((unsigned)((jb + gp*16 + vrl) * LDH + gd*16 + vcl) << 1);
                ldm_x4_t(vh[gd][0], vh[gd][1], vh[gd][2], vh[gd][3], addr);
                ldm_x4_t(vl[gd][0], vl[gd][1], vl[gd][2], vl[gd][3], addr + SKP*2);
            }
#pragma unroll
            for (int gd = 0; gd < 4; gd++) {
                mma_bf16(o[2*gd][0], o[2*gd][1], o[2*gd][2], o[2*gd][3],
                         aPh[0], aPh[1], aPh[2], aPh[3], vh[gd][0], vh[gd][1]);
                mma_bf16(o[2*gd+1][0], o[2*gd+1][1], o[2*gd+1][2], o[2*gd+1][3],
                         aPh[0], aPh[1], aPh[2], aPh[3], vh[gd][2], vh[gd][3]);
            }
#pragma unroll
            for (int gd = 0; gd < 4; gd++) {
                mma_bf16(o[2*gd][0], o[2*gd][1], o[2*gd][2], o[2*gd][3],
                         aPl[0], aPl[1], aPl[2], aPl[3], vh[gd][0], vh[gd][1]);
                mma_bf16(o[2*gd+1][0], o[2*gd+1][1], o[2*gd+1][2], o[2*gd+1][3],
                         aPl[0], aPl[1], aPl[2], aPl[3], vh[gd][2], vh[gd][3]);
            }
#pragma unroll
            for (int gd = 0; gd < 4; gd++) {
                mma_bf16(o[2*gd][0], o[2*gd][1], o[2*gd][2], o[2*gd][3],
                         aPh[0], aPh[1], aPh[2], aPh[3], vl[gd][0], vl[gd][1]);
                mma_bf16(o[2*gd+1][0], o[2*gd+1][1], o[2*gd+1][2], o[2*gd+1][3],
                         aPh[0], aPh[1], aPh[2], aPh[3], vl[gd][2], vl[gd][3]);
            }
        }
    }

    float inv0 = 1.f / l0, inv1 = 1.f / l1;
    int go0 = base + c * CL_ + qr0;
    int go1 = base + c * CL_ + qr1;
    if ((lane & 3) == 0) {
        g_slog[go0] = m0 + logf(l0);
        g_slog[go1] = m1 + logf(l1);
    }
#pragma unroll
    for (int j = 0; j < 8; j++) {
        int col = j*8 + (lane&3)*2;
        *(float2*)(g_so + (size_t)go0 * D_ + col) = make_float2(o[j][0]*inv0, o[j][1]*inv0);
        *(float2*)(g_so + (size_t)go1 * D_ + col) = make_float2(o[j][2]*inv1, o[j][3]*inv1);
    }
}

// ---------------- unsort + combine hash rounds (fused 2-way bf16 split) ----------------
__global__ __launch_bounds__(256) void combine_kernel()
{
    int idx  = blockIdx.x * 256 + threadIdx.x;
    int d    = idx & 63;
    int rowi = idx >> 6;
    int t    = rowi & (T_-1);
    int bh   = rowi >> 12;
    int b = bh / H_, h = bh % H_;
    int p0 = g_undo[bh * TOTAL_ + t];
    int p1 = g_undo[bh * TOTAL_ + T_ + t];
    float l0 = g_slog[bh * TOTAL_ + p0];
    float l1 = g_slog[bh * TOTAL_ + p1];
    float mm = fmaxf(l0, l1);
    float w0 = __expf(l0 - mm), w1 = __expf(l1 - mm);
    float inv = 1.f / (w0 + w1);
    float o0 = g_so[((size_t)(bh * TOTAL_ + p0)) * D_ + d];
    float o1 = g_so[((size_t)(bh * TOTAL_ + p1)) * D_ + d];
    float val = (w0 * o0 + w1 * o1) * inv;
    size_t oidx = ((size_t)(b * T_ + t)) * HID_ + h * D_ + d;
    __nv_bfloat16 hi = __float2bfloat16(val);
    g_as[oidx] = hi;
    g_as[(size_t)M_ * HID_ + oidx] = __float2bfloat16(val - __bfloat162float(hi));
}

// ---------------- launcher ----------------
extern "C" void kernel_launch(void* const* d_in, const int* in_sizes, int n_in,
                              void* d_out, int out_size)
{
    const float* X    = (const float*)d_in[0];
    const float* mask = (const float*)d_in[1];
    const float* W_qk = (const float*)d_in[2];
    const float* W_v  = (const float*)d_in[3];
    const float* rot  = (const float*)d_in[4];
    const float* W_to = (const float*)d_in[5];
    const float* b_to = (const float*)d_in[6];
    const float* W_o  = (const float*)d_in[7];
    const float* b_o  = (const float*)d_in[8];
    float* out = (float*)d_out;

    cudaFuncSetAttribute(mma_gemm_kernel, cudaFuncAttributeMaxDynamicSharedMemorySize, GEMM_SMEM_MAX);
    cudaFuncSetAttribute(attn2_kernel,    cudaFuncAttributeMaxDynamicSharedMemorySize, AT2_SMEM_B);

    const int NX4 = M_ * HID_ / 4;
    const int NW4 = HID_ * HID_ / 4;
    const int GX  = (NX4 + 255) / 256;
    const int GW  = (NW4 + 255) / 256;
    dim3 gg(HID_ / 64, M_ / 128);   // (12, 128)

    // QK projection: bf16 3-way split, 6 passes (bit-identical to proven R13 buckets)
    split_kernel<<<GX, 256>>>(X,    NX4, 3, 0, 0);
    split_kernel<<<GW, 256>>>(W_qk, NW4, 3, 1, 0);
    mma_gemm_kernel<<<gg, 256, 2*STAGE3_B>>>(nullptr, 1, 3);   // -> g_qk
    split_kernel<<<GW, 256>>>(W_v,  NW4, 2, 1, 0);
    mma_gemm_kernel<<<gg, 256, 2*STAGE2_B>>>(nullptr, 2, 2);   // -> g_v16 planes

    prepbucket_kernel<<<(BH_ * T_) / 8, 256>>>(rot);
    hist_kernel<<<BH_, 256>>>();
    scatter_kernel<<<dim3(NBTOT_, BH_), 256>>>();

    attn2_kernel<<<dim3(NCH_, BH_), 256, AT2_SMEM_B>>>(mask);

    combine_kernel<<<(BH_ * T_ * D_) / 256, 256>>>();          // -> g_as planes

    // combined output weight: W_c = W_o @ W_to (transpose fused), b_c = b_o + W_o @ b_to
    sgemm768_kernel<<<dim3(HID_/64, HID_/128), 256>>>(W_o, W_to);
    biascomb_kernel<<<(HID_ + 255)/256, 256>>>(b_to, b_o, W_o);
    split_kernel<<<GW, 256>>>(nullptr, NW4, 2, 1, 3);          // g_wc -> g_bs

    mma_gemm_kernel<<<gg, 256, 2*STAGE2_B>>>(out, 4, 2);       // -> d_out
}